// round 5
// baseline (speedup 1.0000x reference)
#include <cuda_runtime.h>
#include <cuda_bf16.h>
#include <cstdint>

#define TT   3072
#define HID  4096
#define NH   32
#define HD   128
#define NBAT 4
#define MAXB 24

// ============================================================================
// helpers (baseline PTX only — no sm_103a-gated features)
// ============================================================================
__device__ __forceinline__ uint32_t smem_to_u32(const void* p) {
    uint32_t a;
    asm("{ .reg .u64 t; cvta.to.shared.u64 t, %1; cvt.u32.u64 %0, t; }" : "=r"(a) : "l"(p));
    return a;
}
__device__ __forceinline__ void cp16(uint32_t dst, const void* src) {
    asm volatile("cp.async.cg.shared.global [%0], [%1], 16;" :: "r"(dst), "l"(src));
}
#define CP_COMMIT() asm volatile("cp.async.commit_group;" ::: "memory")
#define CP_WAIT2()  asm volatile("cp.async.wait_group 2;" ::: "memory")

__device__ __forceinline__ void ldsm4(uint32_t* r, uint32_t addr) {
    asm volatile("ldmatrix.sync.aligned.m8n8.x4.shared.b16 {%0,%1,%2,%3}, [%4];"
        : "=r"(r[0]), "=r"(r[1]), "=r"(r[2]), "=r"(r[3]) : "r"(addr));
}
__device__ __forceinline__ void mma_bf16(float* c, const uint32_t* a, const uint32_t* b) {
    asm volatile("mma.sync.aligned.m16n8k16.row.col.f32.bf16.bf16.f32 "
        "{%0,%1,%2,%3}, {%4,%5,%6,%7}, {%8,%9}, {%0,%1,%2,%3};"
        : "+f"(c[0]), "+f"(c[1]), "+f"(c[2]), "+f"(c[3])
        : "r"(a[0]), "r"(a[1]), "r"(a[2]), "r"(a[3]), "r"(b[0]), "r"(b[1]));
}

// ---- workspace (static device arrays; no allocation) ----
__device__ float g_q[(size_t)TT * HID];
__device__ float g_k[(size_t)TT * HID];
__device__ float g_v[(size_t)TT * HID];
__device__ float g_o[(size_t)TT * HID];
__device__ float g_freq[64];
__device__ __nv_bfloat16 g_xhi[(size_t)TT * HID];
__device__ __nv_bfloat16 g_xlo[(size_t)TT * HID];
__device__ __nv_bfloat16 g_w1hi[(size_t)HID * HID];
__device__ __nv_bfloat16 g_w1lo[(size_t)HID * HID];
__device__ __nv_bfloat16 g_w2hi[(size_t)HID * HID];
__device__ __nv_bfloat16 g_w2lo[(size_t)HID * HID];
__device__ __nv_bfloat16 g_w3hi[(size_t)HID * HID];
__device__ __nv_bfloat16 g_w3lo[(size_t)HID * HID];
__device__ __nv_bfloat16 g_w4hi[(size_t)HID * HID];
__device__ __nv_bfloat16 g_w4lo[(size_t)HID * HID];

__global__ void init_freq_kernel() {
    int i = threadIdx.x;
    if (i < 64) g_freq[i] = (float)exp(-(double)i * (log(10000.0) / 64.0));
}

// ============================================================================
// fp32 -> bf16 hi/lo split
// ============================================================================
__device__ __forceinline__ void split_body(const float* __restrict__ x,
                                           __nv_bfloat16* __restrict__ hi,
                                           __nv_bfloat16* __restrict__ lo, int i)
{
    float4 v = ((const float4*)x)[i];
    float vv[4] = {v.x, v.y, v.z, v.w};
    __nv_bfloat16 h[4], l[4];
#pragma unroll
    for (int j = 0; j < 4; j++) {
        h[j] = __float2bfloat16(vv[j]);
        l[j] = __float2bfloat16(vv[j] - __bfloat162float(h[j]));
    }
    ((__nv_bfloat162*)hi)[2 * i + 0] = __nv_bfloat162(h[0], h[1]);
    ((__nv_bfloat162*)hi)[2 * i + 1] = __nv_bfloat162(h[2], h[3]);
    ((__nv_bfloat162*)lo)[2 * i + 0] = __nv_bfloat162(l[0], l[1]);
    ((__nv_bfloat162*)lo)[2 * i + 1] = __nv_bfloat162(l[2], l[3]);
}

__global__ __launch_bounds__(256) void split_kernel(
    const float* __restrict__ x, __nv_bfloat16* __restrict__ hi,
    __nv_bfloat16* __restrict__ lo, int n4)
{
    int i = blockIdx.x * blockDim.x + threadIdx.x;
    if (i >= n4) return;
    split_body(x, hi, lo, i);
}

// all 4 weight matrices in one launch (blockIdx.z selects)
__global__ __launch_bounds__(256) void wsplit_kernel(
    const float* __restrict__ Wq, const float* __restrict__ Wk,
    const float* __restrict__ Wv, const float* __restrict__ Wo)
{
    int i = blockIdx.x * blockDim.x + threadIdx.x;
    const int n4 = HID * HID / 4;
    if (i >= n4) return;
    int z = blockIdx.z;
    const float* src = (z == 0) ? Wq : (z == 1) ? Wk : (z == 2) ? Wv : Wo;
    __nv_bfloat16* hi = (z == 0) ? g_w1hi : (z == 1) ? g_w2hi : (z == 2) ? g_w3hi : g_w4hi;
    __nv_bfloat16* lo = (z == 0) ? g_w1lo : (z == 1) ? g_w2lo : (z == 2) ? g_w3lo : g_w4lo;
    split_body(src, hi, lo, i);
}

// ============================================================================
// mma.sync GEMM: C[3072,4096] = A @ B^T + bias, 3-term bf16 split.
// CTA 128x128, BK=64, 16 warps (4x4), warp tile 32x32, cp.async 3-stage.
// ============================================================================
#define STAGES  3
#define TILE_B  16384
#define STAGE_B (4 * TILE_B)
#define GEMM_SMEM (STAGES * STAGE_B)   // 196608

__global__ __launch_bounds__(512)
void gemm3(const __nv_bfloat16* __restrict__ Ahi, const __nv_bfloat16* __restrict__ Alo,
           const __nv_bfloat16* __restrict__ Bhi, const __nv_bfloat16* __restrict__ Blo,
           const float* __restrict__ bias, float* __restrict__ C)
{
    extern __shared__ char smem[];
    const uint32_t sb = smem_to_u32(smem);
    const int tid = threadIdx.x;
    const int wid = tid >> 5;
    const int lane = tid & 31;
    const int m0 = blockIdx.y << 7;
    const int n0 = blockIdx.x << 7;
    const int wm = wid >> 2;        // 0..3
    const int wn = wid & 3;         // 0..3

    // ---- loader setup: 4 threads per row, 2x16B each, 4 tiles ----
    const int lrow = tid >> 2;              // 0..127
    const int lcb  = (tid & 3) * 2;         // 16B-chunk base 0,2,4,6
    const uint32_t lrsw = (uint32_t)(lrow & 7) << 4;
    const __nv_bfloat16* gsrc[4];
    gsrc[0] = Ahi + (size_t)(m0 + lrow) * HID + lcb * 8;
    gsrc[1] = Alo + (size_t)(m0 + lrow) * HID + lcb * 8;
    gsrc[2] = Bhi + (size_t)(n0 + lrow) * HID + lcb * 8;
    gsrc[3] = Blo + (size_t)(n0 + lrow) * HID + lcb * 8;
    uint32_t ldst[4][2];
#pragma unroll
    for (int t = 0; t < 4; t++)
#pragma unroll
        for (int j = 0; j < 2; j++)
            ldst[t][j] = t * TILE_B + lrow * 128 + ((uint32_t)((lcb + j) * 16) ^ lrsw);

    // ---- fragment address setup ----
    uint32_t a_off[2], a_sw[2];
#pragma unroll
    for (int mt = 0; mt < 2; mt++) {
        int m = wm * 32 + mt * 16 + (lane & 15);
        a_off[mt] = (uint32_t)m * 128;
        a_sw[mt]  = (uint32_t)(m & 7) << 4;
    }
    const uint32_t ka = (uint32_t)((lane >> 4) << 4);   // 0 | 16
    uint32_t b_off[2], b_sw[2];
#pragma unroll
    for (int p = 0; p < 2; p++) {
        int n = wn * 32 + p * 16 + (lane & 7) + ((lane & 16) >> 1);
        b_off[p] = (uint32_t)n * 128;
        b_sw[p]  = (uint32_t)(n & 7) << 4;
    }
    const uint32_t kb = (uint32_t)((lane & 8) << 1);    // 0 | 16

    float acc[2][4][4];
#pragma unroll
    for (int i = 0; i < 2; i++)
#pragma unroll
        for (int j = 0; j < 4; j++)
#pragma unroll
            for (int k = 0; k < 4; k++) acc[i][j][k] = 0.f;

    // ---- prologue: load chunks 0,1 ----
#pragma unroll
    for (int s = 0; s < 2; s++) {
        uint32_t base = sb + s * STAGE_B;
#pragma unroll
        for (int t = 0; t < 4; t++) {
            const __nv_bfloat16* src = gsrc[t] + s * 64;
#pragma unroll
            for (int j = 0; j < 2; j++)
                cp16(base + ldst[t][j], src + j * 8);
        }
        CP_COMMIT();
    }

    for (int c = 0; c < 64; c++) {
        const int ldc = c + 2;
        if (ldc < 64) {
            uint32_t base = sb + (ldc % 3) * STAGE_B;
#pragma unroll
            for (int t = 0; t < 4; t++) {
                const __nv_bfloat16* src = gsrc[t] + ldc * 64;
#pragma unroll
                for (int j = 0; j < 2; j++)
                    cp16(base + ldst[t][j], src + j * 8);
            }
        }
        CP_COMMIT();
        CP_WAIT2();
        __syncthreads();

        const uint32_t stb = sb + (c % 3) * STAGE_B;
#pragma unroll
        for (int ks = 0; ks < 4; ks++) {
            uint32_t ahi[2][4], alo[2][4];
#pragma unroll
            for (int mt = 0; mt < 2; mt++) {
                uint32_t ko = ((uint32_t)(ks * 32) + ka) ^ a_sw[mt];
                uint32_t ad = stb + a_off[mt] + ko;
                ldsm4(ahi[mt], ad);
                ldsm4(alo[mt], ad + TILE_B);
            }
            uint32_t bhi[2][4], blo[2][4];
#pragma unroll
            for (int p = 0; p < 2; p++) {
                uint32_t ko = ((uint32_t)(ks * 32) + kb) ^ b_sw[p];
                uint32_t bd = stb + 2 * TILE_B + b_off[p] + ko;
                ldsm4(bhi[p], bd);
                ldsm4(blo[p], bd + TILE_B);
            }
#pragma unroll
            for (int mt = 0; mt < 2; mt++)
#pragma unroll
                for (int nt = 0; nt < 4; nt++) {
                    const uint32_t* bh = &bhi[nt >> 1][2 * (nt & 1)];
                    const uint32_t* bl = &blo[nt >> 1][2 * (nt & 1)];
                    mma_bf16(acc[mt][nt], ahi[mt], bh);
                    mma_bf16(acc[mt][nt], ahi[mt], bl);
                    mma_bf16(acc[mt][nt], alo[mt], bh);
                }
        }
        __syncthreads();
    }

    // ---- epilogue: bias add + store ----
#pragma unroll
    for (int mt = 0; mt < 2; mt++) {
#pragma unroll
        for (int nt = 0; nt < 4; nt++) {
            int row = m0 + wm * 32 + mt * 16 + (lane >> 2);
            int col = n0 + wn * 32 + nt * 8 + 2 * (lane & 3);
            float2 bv = *(const float2*)&bias[col];
            float2 v0, v1;
            v0.x = acc[mt][nt][0] + bv.x; v0.y = acc[mt][nt][1] + bv.y;
            v1.x = acc[mt][nt][2] + bv.x; v1.y = acc[mt][nt][3] + bv.y;
            *(float2*)&C[(size_t)row * HID + col]       = v0;
            *(float2*)&C[(size_t)(row + 8) * HID + col] = v1;
        }
    }
}

// ============================================================================
// RoPE on packed q,k in place (angle in f32 like reference, trig in double)
// ============================================================================
__global__ void rope_kernel(const int* __restrict__ pos) {
    int idx = blockIdx.x * blockDim.x + threadIdx.x;
    if (idx >= TT * NH * 64) return;
    int i = idx & 63;
    int h = (idx >> 6) & 31;
    int t = idx >> 11;
    float p = (float)pos[t];
    float ang = p * g_freq[i];
    double ad = (double)ang;
    float c = (float)cos(ad);
    float s = (float)sin(ad);
    size_t base = ((size_t)t * NH + h) * HD;
    float x1 = g_q[base + i], x2 = g_q[base + 64 + i];
    g_q[base + i]      = x1 * c - x2 * s;
    g_q[base + 64 + i] = x2 * c + x1 * s;
    float y1 = g_k[base + i], y2 = g_k[base + 64 + i];
    g_k[base + i]      = y1 * c - y2 * s;
    g_k[base + 64 + i] = y2 * c + y1 * s;
}

// ============================================================================
// Flash attention (fp32), validated in round 1
// ============================================================================
#define ATTN_SMEM_FLOATS (8192 + 8448 + 4224 + 192)
#define ATTN_SMEM_BYTES  (ATTN_SMEM_FLOATS * 4)

__global__ __launch_bounds__(128) void attn_kernel(
    const float* __restrict__ past_k, const float* __restrict__ past_v,
    const int* __restrict__ q_start, const int* __restrict__ q_lens,
    const int* __restrict__ kv_lens, const int* __restrict__ boff)
{
    extern __shared__ float sm[];
    float* Qs   = sm;
    float* KVs  = sm + 8192;
    float* Ps   = KVs + 8448;
    float* mrow = Ps + 4224;
    float* lrow = mrow + 64;
    float* arow = lrow + 64;

    const int b = blockIdx.z, h = blockIdx.y, qt = blockIdx.x;
    const int qlen = q_lens[b];
    if (qt * 64 >= qlen) return;
    const int qs0 = q_start[b];
    const int kvlen = kv_lens[b];
    const int hist = kvlen - qlen;
    const int tid = threadIdx.x;
    const float scale = 0.08838834764831845f;
    const float NEGINF = __int_as_float(0xff800000);

    const int c4 = (tid & 31) << 2;
    const int r0 = tid >> 5;

#pragma unroll
    for (int rr = 0; rr < 16; rr++) {
        int r = r0 + rr * 4;
        int qglob = qt * 64 + r;
        float4 v = make_float4(0.f, 0.f, 0.f, 0.f);
        if (qglob < qlen)
            v = *(const float4*)&g_q[((size_t)(qs0 + qglob) * NH + h) * HD + c4];
        *(float4*)&Qs[r * 128 + c4] = v;
    }
    if (tid < 64) { mrow[tid] = NEGINF; lrow[tid] = 0.f; }
    __syncthreads();

    const int tq = tid >> 3;
    const int tk = tid & 7;

    float o[4][16];
#pragma unroll
    for (int i = 0; i < 4; i++)
#pragma unroll
        for (int j = 0; j < 16; j++) o[i][j] = 0.f;

    const int qhi  = min(qt * 64 + 63, qlen - 1);
    const int nblk = min((kvlen + 63) >> 6, ((hist + qhi) >> 6) + 1);

    for (int kb = 0; kb < nblk; kb++) {
#pragma unroll
        for (int rr = 0; rr < 16; rr++) {
            int r = r0 + rr * 4;
            int p = kb * 64 + r;
            int pc = min(p, kvlen - 1);
            const float* src;
            if (pc < hist) {
                int blk = boff[b * MAXB + (pc >> 6)];
                src = past_k + ((size_t)(blk * 64 + (pc & 63)) * NH + h) * HD;
            } else {
                src = g_k + ((size_t)(qs0 + pc - hist) * NH + h) * HD;
            }
            *(float4*)&KVs[r * 132 + c4] = *(const float4*)&src[c4];
        }
        __syncthreads();

        float s[4][8];
#pragma unroll
        for (int i = 0; i < 4; i++)
#pragma unroll
            for (int m = 0; m < 8; m++) s[i][m] = 0.f;
#pragma unroll 4
        for (int d = 0; d < 128; d += 4) {
            float4 qv[4];
#pragma unroll
            for (int i = 0; i < 4; i++)
                qv[i] = *(const float4*)&Qs[(tq * 4 + i) * 128 + d];
#pragma unroll
            for (int m = 0; m < 8; m++) {
                float4 kv = *(const float4*)&KVs[(tk + 8 * m) * 132 + d];
#pragma unroll
                for (int i = 0; i < 4; i++)
                    s[i][m] += qv[i].x * kv.x + qv[i].y * kv.y + qv[i].z * kv.z + qv[i].w * kv.w;
            }
        }
#pragma unroll
        for (int i = 0; i < 4; i++) {
            int qglob = qt * 64 + tq * 4 + i;
#pragma unroll
            for (int m = 0; m < 8; m++) {
                int kg = kb * 64 + tk + 8 * m;
                float val = (kg <= hist + qglob) ? s[i][m] * scale : NEGINF;
                Ps[(tq * 4 + i) * 66 + tk + 8 * m] = val;
            }
        }
        __syncthreads();

#pragma unroll
        for (int rr = 0; rr < 16; rr++) {
            int r = r0 + rr * 4;
            int p = kb * 64 + r;
            int pc = min(p, kvlen - 1);
            const float* src;
            if (pc < hist) {
                int blk = boff[b * MAXB + (pc >> 6)];
                src = past_v + ((size_t)(blk * 64 + (pc & 63)) * NH + h) * HD;
            } else {
                src = g_v + ((size_t)(qs0 + pc - hist) * NH + h) * HD;
            }
            *(float4*)&KVs[r * 132 + c4] = *(const float4*)&src[c4];
        }

        if (tid < 64) {
            int r = tid;
            float mo = mrow[r];
            float mx = mo;
#pragma unroll 8
            for (int j = 0; j < 64; j++) mx = fmaxf(mx, Ps[r * 66 + j]);
            float alpha = expf(mo - mx);
            float sum = 0.f;
#pragma unroll 8
            for (int j = 0; j < 64; j++) {
                float pj = expf(Ps[r * 66 + j] - mx);
                Ps[r * 66 + j] = pj;
                sum += pj;
            }
            mrow[r] = mx;
            lrow[r] = lrow[r] * alpha + sum;
            arow[r] = alpha;
        }
        __syncthreads();

#pragma unroll
        for (int i = 0; i < 4; i++) {
            float a = arow[tq * 4 + i];
#pragma unroll
            for (int j = 0; j < 16; j++) o[i][j] *= a;
        }
#pragma unroll 2
        for (int k = 0; k < 64; k++) {
            float pr[4];
#pragma unroll
            for (int i = 0; i < 4; i++) pr[i] = Ps[(tq * 4 + i) * 66 + k];
#pragma unroll
            for (int m = 0; m < 4; m++) {
                float4 vv = *(const float4*)&KVs[k * 132 + tk * 4 + 32 * m];
#pragma unroll
                for (int i = 0; i < 4; i++) {
                    o[i][m * 4 + 0] += pr[i] * vv.x;
                    o[i][m * 4 + 1] += pr[i] * vv.y;
                    o[i][m * 4 + 2] += pr[i] * vv.z;
                    o[i][m * 4 + 3] += pr[i] * vv.w;
                }
            }
        }
        __syncthreads();
    }

#pragma unroll
    for (int i = 0; i < 4; i++) {
        int qglob = qt * 64 + tq * 4 + i;
        if (qglob >= qlen) continue;
        float inv = 1.f / lrow[tq * 4 + i];
        size_t base = ((size_t)(qs0 + qglob) * NH + h) * HD;
#pragma unroll
        for (int m = 0; m < 4; m++) {
            float4 w;
            w.x = o[i][m * 4 + 0] * inv;
            w.y = o[i][m * 4 + 1] * inv;
            w.z = o[i][m * 4 + 2] * inv;
            w.w = o[i][m * 4 + 3] * inv;
            *(float4*)&g_o[base + tk * 4 + 32 * m] = w;
        }
    }
}

// ============================================================================
extern "C" void kernel_launch(void* const* d_in, const int* in_sizes, int n_in,
                              void* d_out, int out_size) {
    const float* x      = (const float*)d_in[0];
    const int*   pos    = (const int*)d_in[1];
    const int*   qstart = (const int*)d_in[2];
    const int*   qlens  = (const int*)d_in[3];
    const int*   kvlens = (const int*)d_in[4];
    const int*   boff   = (const int*)d_in[5];
    const float* pk     = (const float*)d_in[6];
    const float* pv     = (const float*)d_in[7];
    const float* Wq = (const float*)d_in[8];
    const float* bq = (const float*)d_in[9];
    const float* Wk = (const float*)d_in[10];
    const float* bk = (const float*)d_in[11];
    const float* Wv = (const float*)d_in[12];
    const float* bv = (const float*)d_in[13];
    const float* Wo = (const float*)d_in[14];
    const float* bo = (const float*)d_in[15];
    float* out = (float*)d_out;

    float *qp, *kp, *vp, *op;
    cudaGetSymbolAddress((void**)&qp, g_q);
    cudaGetSymbolAddress((void**)&kp, g_k);
    cudaGetSymbolAddress((void**)&vp, g_v);
    cudaGetSymbolAddress((void**)&op, g_o);
    __nv_bfloat16 *xhi, *xlo, *w1hi, *w1lo, *w2hi, *w2lo, *w3hi, *w3lo, *w4hi, *w4lo;
    cudaGetSymbolAddress((void**)&xhi, g_xhi);
    cudaGetSymbolAddress((void**)&xlo, g_xlo);
    cudaGetSymbolAddress((void**)&w1hi, g_w1hi);
    cudaGetSymbolAddress((void**)&w1lo, g_w1lo);
    cudaGetSymbolAddress((void**)&w2hi, g_w2hi);
    cudaGetSymbolAddress((void**)&w2lo, g_w2lo);
    cudaGetSymbolAddress((void**)&w3hi, g_w3hi);
    cudaGetSymbolAddress((void**)&w3lo, g_w3lo);
    cudaGetSymbolAddress((void**)&w4hi, g_w4hi);
    cudaGetSymbolAddress((void**)&w4lo, g_w4lo);

    cudaFuncSetAttribute(gemm3, cudaFuncAttributeMaxDynamicSharedMemorySize, GEMM_SMEM);
    cudaFuncSetAttribute(attn_kernel, cudaFuncAttributeMaxDynamicSharedMemorySize, ATTN_SMEM_BYTES);

    const int n4x = TT * HID / 4;
    const int n4w = HID * HID / 4;
    dim3 gg(HID / 128, TT / 128);   // (32, 24)

    // 0: all weight splits (one launch, z selects matrix; Wo pre-split here)
    wsplit_kernel<<<dim3((n4w + 255) / 256, 1, 4), 256>>>(Wq, Wk, Wv, Wo);
    // 1: activation split
    split_kernel<<<(n4x + 255) / 256, 256>>>(x, xhi, xlo, n4x);
    // 2,3,4: Q/K/V GEMMs  (ncu capture window lands here)
    gemm3<<<gg, 512, GEMM_SMEM>>>(xhi, xlo, w1hi, w1lo, bq, qp);
    gemm3<<<gg, 512, GEMM_SMEM>>>(xhi, xlo, w2hi, w2lo, bk, kp);
    gemm3<<<gg, 512, GEMM_SMEM>>>(xhi, xlo, w3hi, w3lo, bv, vp);
    // 5: freq table, 6: rope, 7: attention
    init_freq_kernel<<<1, 64>>>();
    rope_kernel<<<(TT * NH * 64 + 255) / 256, 256>>>(pos);
    attn_kernel<<<dim3(16, NH, NBAT), 128, ATTN_SMEM_BYTES>>>(pk, pv, qstart, qlens,
                                                              kvlens, boff);
    // 8: split attention output, 9: O projection
    split_kernel<<<(n4x + 255) / 256, 256>>>(op, xhi, xlo, n4x);
    gemm3<<<gg, 512, GEMM_SMEM>>>(xhi, xlo, w4hi, w4lo, bo, out);
}

// round 6
// speedup vs baseline: 1.3600x; 1.3600x over previous
#include <cuda_runtime.h>
#include <cuda_bf16.h>
#include <cstdint>

#define TT   3072
#define HID  4096
#define NH   32
#define HD   128
#define NBAT 4
#define MAXB 24

// ============================================================================
// helpers (baseline PTX only — no sm_103a-gated features)
// ============================================================================
__device__ __forceinline__ uint32_t smem_to_u32(const void* p) {
    uint32_t a;
    asm("{ .reg .u64 t; cvta.to.shared.u64 t, %1; cvt.u32.u64 %0, t; }" : "=r"(a) : "l"(p));
    return a;
}
__device__ __forceinline__ void cp16(uint32_t dst, const void* src) {
    asm volatile("cp.async.cg.shared.global [%0], [%1], 16;" :: "r"(dst), "l"(src));
}
#define CP_COMMIT() asm volatile("cp.async.commit_group;" ::: "memory")
#define CP_WAIT2()  asm volatile("cp.async.wait_group 2;" ::: "memory")

__device__ __forceinline__ void ldsm4(uint32_t* r, uint32_t addr) {
    asm volatile("ldmatrix.sync.aligned.m8n8.x4.shared.b16 {%0,%1,%2,%3}, [%4];"
        : "=r"(r[0]), "=r"(r[1]), "=r"(r[2]), "=r"(r[3]) : "r"(addr));
}
__device__ __forceinline__ void mma_bf16(float* c, const uint32_t* a, const uint32_t* b) {
    asm volatile("mma.sync.aligned.m16n8k16.row.col.f32.bf16.bf16.f32 "
        "{%0,%1,%2,%3}, {%4,%5,%6,%7}, {%8,%9}, {%0,%1,%2,%3};"
        : "+f"(c[0]), "+f"(c[1]), "+f"(c[2]), "+f"(c[3])
        : "r"(a[0]), "r"(a[1]), "r"(a[2]), "r"(a[3]), "r"(b[0]), "r"(b[1]));
}

// ---- workspace (static device arrays; no allocation) ----
__device__ float g_q[(size_t)TT * HID];
__device__ float g_k[(size_t)TT * HID];
__device__ float g_v[(size_t)TT * HID];
__device__ float g_o[(size_t)TT * HID];
__device__ float g_freq[64];
__device__ __nv_bfloat16 g_xhi[(size_t)TT * HID];
__device__ __nv_bfloat16 g_xlo[(size_t)TT * HID];
__device__ __nv_bfloat16 g_w1hi[(size_t)HID * HID];
__device__ __nv_bfloat16 g_w1lo[(size_t)HID * HID];
__device__ __nv_bfloat16 g_w2hi[(size_t)HID * HID];
__device__ __nv_bfloat16 g_w2lo[(size_t)HID * HID];
__device__ __nv_bfloat16 g_w3hi[(size_t)HID * HID];
__device__ __nv_bfloat16 g_w3lo[(size_t)HID * HID];
__device__ __nv_bfloat16 g_w4hi[(size_t)HID * HID];
__device__ __nv_bfloat16 g_w4lo[(size_t)HID * HID];

__global__ void init_freq_kernel() {
    int i = threadIdx.x;
    if (i < 64) g_freq[i] = (float)exp(-(double)i * (log(10000.0) / 64.0));
}

// ============================================================================
// fp32 -> bf16 hi/lo split
// ============================================================================
__device__ __forceinline__ void split_body(const float* __restrict__ x,
                                           __nv_bfloat16* __restrict__ hi,
                                           __nv_bfloat16* __restrict__ lo, int i)
{
    float4 v = ((const float4*)x)[i];
    float vv[4] = {v.x, v.y, v.z, v.w};
    __nv_bfloat16 h[4], l[4];
#pragma unroll
    for (int j = 0; j < 4; j++) {
        h[j] = __float2bfloat16(vv[j]);
        l[j] = __float2bfloat16(vv[j] - __bfloat162float(h[j]));
    }
    ((__nv_bfloat162*)hi)[2 * i + 0] = __nv_bfloat162(h[0], h[1]);
    ((__nv_bfloat162*)hi)[2 * i + 1] = __nv_bfloat162(h[2], h[3]);
    ((__nv_bfloat162*)lo)[2 * i + 0] = __nv_bfloat162(l[0], l[1]);
    ((__nv_bfloat162*)lo)[2 * i + 1] = __nv_bfloat162(l[2], l[3]);
}

__global__ __launch_bounds__(256) void split_kernel(
    const float* __restrict__ x, __nv_bfloat16* __restrict__ hi,
    __nv_bfloat16* __restrict__ lo, int n4)
{
    int i = blockIdx.x * blockDim.x + threadIdx.x;
    if (i >= n4) return;
    split_body(x, hi, lo, i);
}

// all 4 weight matrices in one launch (blockIdx.z selects)
__global__ __launch_bounds__(256) void wsplit_kernel(
    const float* __restrict__ Wq, const float* __restrict__ Wk,
    const float* __restrict__ Wv, const float* __restrict__ Wo)
{
    int i = blockIdx.x * blockDim.x + threadIdx.x;
    const int n4 = HID * HID / 4;
    if (i >= n4) return;
    int z = blockIdx.z;
    const float* src = (z == 0) ? Wq : (z == 1) ? Wk : (z == 2) ? Wv : Wo;
    __nv_bfloat16* hi = (z == 0) ? g_w1hi : (z == 1) ? g_w2hi : (z == 2) ? g_w3hi : g_w4hi;
    __nv_bfloat16* lo = (z == 0) ? g_w1lo : (z == 1) ? g_w2lo : (z == 2) ? g_w3lo : g_w4lo;
    split_body(src, hi, lo, i);
}

// ============================================================================
// mma.sync GEMM: C[3072,4096] = A @ B^T + bias, 3-term bf16 split.
// CTA 128x128, BK=32, 8 warps (2x4), warp tile 64x32, cp.async 3-stage.
// Stage = 32KB -> 3 stages = 96KB -> 2 CTAs/SM.
// Packed smem layout: two K32-rows per 128B line, chunk index
//   ((row&1)*4 + cb) ^ ((row>>1)&7)   (conflict-free for ldmatrix)
// ============================================================================
#define STAGES  3
#define TILE_B  8192           // 128 rows x 32 bf16, packed in 64 x 128B lines
#define STAGE_B (4 * TILE_B)   // 32768
#define GEMM_SMEM (STAGES * STAGE_B)   // 98304

__global__ __launch_bounds__(256)
void gemm3(const __nv_bfloat16* __restrict__ Ahi, const __nv_bfloat16* __restrict__ Alo,
           const __nv_bfloat16* __restrict__ Bhi, const __nv_bfloat16* __restrict__ Blo,
           const float* __restrict__ bias, float* __restrict__ C)
{
    extern __shared__ char smem[];
    const uint32_t sb = smem_to_u32(smem);
    const int tid = threadIdx.x;
    const int wid = tid >> 5;
    const int lane = tid & 31;
    const int m0 = blockIdx.y << 7;
    const int n0 = blockIdx.x << 7;
    const int wm = wid >> 2;        // 0..1
    const int wn = wid & 3;         // 0..3

    // ---- loader setup: 2 threads per M-row, 2x16B each, 4 tiles ----
    const int lrow  = tid >> 1;             // 0..127  (M/N row)
    const int jbase = (tid & 1) * 2;        // chunk-in-row base 0 or 2 (row has 4)
    const uint32_t lline = (uint32_t)(lrow >> 1) * 128;
    const uint32_t lmb   = (uint32_t)(lrow & 1) * 4;
    const uint32_t lsw   = (uint32_t)(lrow >> 1) & 7;
    const __nv_bfloat16* gsrc[4];
    gsrc[0] = Ahi + (size_t)(m0 + lrow) * HID + jbase * 8;
    gsrc[1] = Alo + (size_t)(m0 + lrow) * HID + jbase * 8;
    gsrc[2] = Bhi + (size_t)(n0 + lrow) * HID + jbase * 8;
    gsrc[3] = Blo + (size_t)(n0 + lrow) * HID + jbase * 8;
    uint32_t ldst[4][2];
#pragma unroll
    for (int t = 0; t < 4; t++)
#pragma unroll
        for (int j = 0; j < 2; j++)
            ldst[t][j] = t * TILE_B + lline + (((lmb + jbase + j) ^ lsw) << 4);

    // ---- fragment address setup (packed layout) ----
    uint32_t a_line[4], a_mb[4], a_sw[4];
#pragma unroll
    for (int mt = 0; mt < 4; mt++) {
        int m = wm * 64 + mt * 16 + (lane & 15);
        a_line[mt] = (uint32_t)(m >> 1) * 128;
        a_mb[mt]   = (uint32_t)(m & 1) * 4;
        a_sw[mt]   = (uint32_t)(m >> 1) & 7;
    }
    const uint32_t cba = (uint32_t)(lane >> 4);          // 0 | 1 (k-half)
    uint32_t b_line[2], b_mb[2], b_sw[2];
#pragma unroll
    for (int p = 0; p < 2; p++) {
        int n = wn * 32 + p * 16 + (lane & 7) + ((lane & 16) >> 1);
        b_line[p] = (uint32_t)(n >> 1) * 128;
        b_mb[p]   = (uint32_t)(n & 1) * 4;
        b_sw[p]   = (uint32_t)(n >> 1) & 7;
    }
    const uint32_t cbb = (uint32_t)((lane & 8) >> 3);    // 0 | 1 (k-half)

    float acc[4][4][4];
#pragma unroll
    for (int i = 0; i < 4; i++)
#pragma unroll
        for (int j = 0; j < 4; j++)
#pragma unroll
            for (int k = 0; k < 4; k++) acc[i][j][k] = 0.f;

    // ---- prologue: load chunks 0,1 ----
#pragma unroll
    for (int s = 0; s < 2; s++) {
        uint32_t base = sb + s * STAGE_B;
#pragma unroll
        for (int t = 0; t < 4; t++) {
            const __nv_bfloat16* src = gsrc[t] + s * 32;
#pragma unroll
            for (int j = 0; j < 2; j++)
                cp16(base + ldst[t][j], src + j * 8);
        }
        CP_COMMIT();
    }

    for (int c = 0; c < 128; c++) {
        const int ldc = c + 2;
        if (ldc < 128) {
            uint32_t base = sb + (ldc % 3) * STAGE_B;
#pragma unroll
            for (int t = 0; t < 4; t++) {
                const __nv_bfloat16* src = gsrc[t] + ldc * 32;
#pragma unroll
                for (int j = 0; j < 2; j++)
                    cp16(base + ldst[t][j], src + j * 8);
            }
        }
        CP_COMMIT();
        CP_WAIT2();
        __syncthreads();

        const uint32_t stb = sb + (c % 3) * STAGE_B;
#pragma unroll
        for (int ks = 0; ks < 2; ks++) {
            uint32_t ahi[4][4], alo[4][4];
#pragma unroll
            for (int mt = 0; mt < 4; mt++) {
                uint32_t ad = stb + a_line[mt] +
                    (((a_mb[mt] + ks * 2 + cba) ^ a_sw[mt]) << 4);
                ldsm4(ahi[mt], ad);
                ldsm4(alo[mt], ad + TILE_B);
            }
            uint32_t bhi[2][4], blo[2][4];
#pragma unroll
            for (int p = 0; p < 2; p++) {
                uint32_t bd = stb + 2 * TILE_B + b_line[p] +
                    (((b_mb[p] + ks * 2 + cbb) ^ b_sw[p]) << 4);
                ldsm4(bhi[p], bd);
                ldsm4(blo[p], bd + TILE_B);
            }
#pragma unroll
            for (int mt = 0; mt < 4; mt++)
#pragma unroll
                for (int nt = 0; nt < 4; nt++) {
                    const uint32_t* bh = &bhi[nt >> 1][2 * (nt & 1)];
                    const uint32_t* bl = &blo[nt >> 1][2 * (nt & 1)];
                    mma_bf16(acc[mt][nt], ahi[mt], bh);
                    mma_bf16(acc[mt][nt], ahi[mt], bl);
                    mma_bf16(acc[mt][nt], alo[mt], bh);
                }
        }
        __syncthreads();
    }

    // ---- epilogue: bias add + store ----
#pragma unroll
    for (int mt = 0; mt < 4; mt++) {
#pragma unroll
        for (int nt = 0; nt < 4; nt++) {
            int row = m0 + wm * 64 + mt * 16 + (lane >> 2);
            int col = n0 + wn * 32 + nt * 8 + 2 * (lane & 3);
            float2 bv = *(const float2*)&bias[col];
            float2 v0, v1;
            v0.x = acc[mt][nt][0] + bv.x; v0.y = acc[mt][nt][1] + bv.y;
            v1.x = acc[mt][nt][2] + bv.x; v1.y = acc[mt][nt][3] + bv.y;
            *(float2*)&C[(size_t)row * HID + col]       = v0;
            *(float2*)&C[(size_t)(row + 8) * HID + col] = v1;
        }
    }
}

// ============================================================================
// RoPE on packed q,k in place (angle in f32 like reference, trig in double)
// ============================================================================
__global__ void rope_kernel(const int* __restrict__ pos) {
    int idx = blockIdx.x * blockDim.x + threadIdx.x;
    if (idx >= TT * NH * 64) return;
    int i = idx & 63;
    int h = (idx >> 6) & 31;
    int t = idx >> 11;
    float p = (float)pos[t];
    float ang = p * g_freq[i];
    double ad = (double)ang;
    float c = (float)cos(ad);
    float s = (float)sin(ad);
    size_t base = ((size_t)t * NH + h) * HD;
    float x1 = g_q[base + i], x2 = g_q[base + 64 + i];
    g_q[base + i]      = x1 * c - x2 * s;
    g_q[base + 64 + i] = x2 * c + x1 * s;
    float y1 = g_k[base + i], y2 = g_k[base + 64 + i];
    g_k[base + i]      = y1 * c - y2 * s;
    g_k[base + 64 + i] = y2 * c + y1 * s;
}

// ============================================================================
// Flash attention (fp32), validated in round 1
// ============================================================================
#define ATTN_SMEM_FLOATS (8192 + 8448 + 4224 + 192)
#define ATTN_SMEM_BYTES  (ATTN_SMEM_FLOATS * 4)

__global__ __launch_bounds__(128) void attn_kernel(
    const float* __restrict__ past_k, const float* __restrict__ past_v,
    const int* __restrict__ q_start, const int* __restrict__ q_lens,
    const int* __restrict__ kv_lens, const int* __restrict__ boff)
{
    extern __shared__ float sm[];
    float* Qs   = sm;
    float* KVs  = sm + 8192;
    float* Ps   = KVs + 8448;
    float* mrow = Ps + 4224;
    float* lrow = mrow + 64;
    float* arow = lrow + 64;

    const int b = blockIdx.z, h = blockIdx.y, qt = blockIdx.x;
    const int qlen = q_lens[b];
    if (qt * 64 >= qlen) return;
    const int qs0 = q_start[b];
    const int kvlen = kv_lens[b];
    const int hist = kvlen - qlen;
    const int tid = threadIdx.x;
    const float scale = 0.08838834764831845f;
    const float NEGINF = __int_as_float(0xff800000);

    const int c4 = (tid & 31) << 2;
    const int r0 = tid >> 5;

#pragma unroll
    for (int rr = 0; rr < 16; rr++) {
        int r = r0 + rr * 4;
        int qglob = qt * 64 + r;
        float4 v = make_float4(0.f, 0.f, 0.f, 0.f);
        if (qglob < qlen)
            v = *(const float4*)&g_q[((size_t)(qs0 + qglob) * NH + h) * HD + c4];
        *(float4*)&Qs[r * 128 + c4] = v;
    }
    if (tid < 64) { mrow[tid] = NEGINF; lrow[tid] = 0.f; }
    __syncthreads();

    const int tq = tid >> 3;
    const int tk = tid & 7;

    float o[4][16];
#pragma unroll
    for (int i = 0; i < 4; i++)
#pragma unroll
        for (int j = 0; j < 16; j++) o[i][j] = 0.f;

    const int qhi  = min(qt * 64 + 63, qlen - 1);
    const int nblk = min((kvlen + 63) >> 6, ((hist + qhi) >> 6) + 1);

    for (int kb = 0; kb < nblk; kb++) {
#pragma unroll
        for (int rr = 0; rr < 16; rr++) {
            int r = r0 + rr * 4;
            int p = kb * 64 + r;
            int pc = min(p, kvlen - 1);
            const float* src;
            if (pc < hist) {
                int blk = boff[b * MAXB + (pc >> 6)];
                src = past_k + ((size_t)(blk * 64 + (pc & 63)) * NH + h) * HD;
            } else {
                src = g_k + ((size_t)(qs0 + pc - hist) * NH + h) * HD;
            }
            *(float4*)&KVs[r * 132 + c4] = *(const float4*)&src[c4];
        }
        __syncthreads();

        float s[4][8];
#pragma unroll
        for (int i = 0; i < 4; i++)
#pragma unroll
            for (int m = 0; m < 8; m++) s[i][m] = 0.f;
#pragma unroll 4
        for (int d = 0; d < 128; d += 4) {
            float4 qv[4];
#pragma unroll
            for (int i = 0; i < 4; i++)
                qv[i] = *(const float4*)&Qs[(tq * 4 + i) * 128 + d];
#pragma unroll
            for (int m = 0; m < 8; m++) {
                float4 kv = *(const float4*)&KVs[(tk + 8 * m) * 132 + d];
#pragma unroll
                for (int i = 0; i < 4; i++)
                    s[i][m] += qv[i].x * kv.x + qv[i].y * kv.y + qv[i].z * kv.z + qv[i].w * kv.w;
            }
        }
#pragma unroll
        for (int i = 0; i < 4; i++) {
            int qglob = qt * 64 + tq * 4 + i;
#pragma unroll
            for (int m = 0; m < 8; m++) {
                int kg = kb * 64 + tk + 8 * m;
                float val = (kg <= hist + qglob) ? s[i][m] * scale : NEGINF;
                Ps[(tq * 4 + i) * 66 + tk + 8 * m] = val;
            }
        }
        __syncthreads();

#pragma unroll
        for (int rr = 0; rr < 16; rr++) {
            int r = r0 + rr * 4;
            int p = kb * 64 + r;
            int pc = min(p, kvlen - 1);
            const float* src;
            if (pc < hist) {
                int blk = boff[b * MAXB + (pc >> 6)];
                src = past_v + ((size_t)(blk * 64 + (pc & 63)) * NH + h) * HD;
            } else {
                src = g_v + ((size_t)(qs0 + pc - hist) * NH + h) * HD;
            }
            *(float4*)&KVs[r * 132 + c4] = *(const float4*)&src[c4];
        }

        if (tid < 64) {
            int r = tid;
            float mo = mrow[r];
            float mx = mo;
#pragma unroll 8
            for (int j = 0; j < 64; j++) mx = fmaxf(mx, Ps[r * 66 + j]);
            float alpha = expf(mo - mx);
            float sum = 0.f;
#pragma unroll 8
            for (int j = 0; j < 64; j++) {
                float pj = expf(Ps[r * 66 + j] - mx);
                Ps[r * 66 + j] = pj;
                sum += pj;
            }
            mrow[r] = mx;
            lrow[r] = lrow[r] * alpha + sum;
            arow[r] = alpha;
        }
        __syncthreads();

#pragma unroll
        for (int i = 0; i < 4; i++) {
            float a = arow[tq * 4 + i];
#pragma unroll
            for (int j = 0; j < 16; j++) o[i][j] *= a;
        }
#pragma unroll 2
        for (int k = 0; k < 64; k++) {
            float pr[4];
#pragma unroll
            for (int i = 0; i < 4; i++) pr[i] = Ps[(tq * 4 + i) * 66 + k];
#pragma unroll
            for (int m = 0; m < 4; m++) {
                float4 vv = *(const float4*)&KVs[k * 132 + tk * 4 + 32 * m];
#pragma unroll
                for (int i = 0; i < 4; i++) {
                    o[i][m * 4 + 0] += pr[i] * vv.x;
                    o[i][m * 4 + 1] += pr[i] * vv.y;
                    o[i][m * 4 + 2] += pr[i] * vv.z;
                    o[i][m * 4 + 3] += pr[i] * vv.w;
                }
            }
        }
        __syncthreads();
    }

#pragma unroll
    for (int i = 0; i < 4; i++) {
        int qglob = qt * 64 + tq * 4 + i;
        if (qglob >= qlen) continue;
        float inv = 1.f / lrow[tq * 4 + i];
        size_t base = ((size_t)(qs0 + qglob) * NH + h) * HD;
#pragma unroll
        for (int m = 0; m < 4; m++) {
            float4 w;
            w.x = o[i][m * 4 + 0] * inv;
            w.y = o[i][m * 4 + 1] * inv;
            w.z = o[i][m * 4 + 2] * inv;
            w.w = o[i][m * 4 + 3] * inv;
            *(float4*)&g_o[base + tk * 4 + 32 * m] = w;
        }
    }
}

// ============================================================================
extern "C" void kernel_launch(void* const* d_in, const int* in_sizes, int n_in,
                              void* d_out, int out_size) {
    const float* x      = (const float*)d_in[0];
    const int*   pos    = (const int*)d_in[1];
    const int*   qstart = (const int*)d_in[2];
    const int*   qlens  = (const int*)d_in[3];
    const int*   kvlens = (const int*)d_in[4];
    const int*   boff   = (const int*)d_in[5];
    const float* pk     = (const float*)d_in[6];
    const float* pv     = (const float*)d_in[7];
    const float* Wq = (const float*)d_in[8];
    const float* bq = (const float*)d_in[9];
    const float* Wk = (const float*)d_in[10];
    const float* bk = (const float*)d_in[11];
    const float* Wv = (const float*)d_in[12];
    const float* bv = (const float*)d_in[13];
    const float* Wo = (const float*)d_in[14];
    const float* bo = (const float*)d_in[15];
    float* out = (float*)d_out;

    float *qp, *kp, *vp, *op;
    cudaGetSymbolAddress((void**)&qp, g_q);
    cudaGetSymbolAddress((void**)&kp, g_k);
    cudaGetSymbolAddress((void**)&vp, g_v);
    cudaGetSymbolAddress((void**)&op, g_o);
    __nv_bfloat16 *xhi, *xlo, *w1hi, *w1lo, *w2hi, *w2lo, *w3hi, *w3lo, *w4hi, *w4lo;
    cudaGetSymbolAddress((void**)&xhi, g_xhi);
    cudaGetSymbolAddress((void**)&xlo, g_xlo);
    cudaGetSymbolAddress((void**)&w1hi, g_w1hi);
    cudaGetSymbolAddress((void**)&w1lo, g_w1lo);
    cudaGetSymbolAddress((void**)&w2hi, g_w2hi);
    cudaGetSymbolAddress((void**)&w2lo, g_w2lo);
    cudaGetSymbolAddress((void**)&w3hi, g_w3hi);
    cudaGetSymbolAddress((void**)&w3lo, g_w3lo);
    cudaGetSymbolAddress((void**)&w4hi, g_w4hi);
    cudaGetSymbolAddress((void**)&w4lo, g_w4lo);

    cudaFuncSetAttribute(gemm3, cudaFuncAttributeMaxDynamicSharedMemorySize, GEMM_SMEM);
    cudaFuncSetAttribute(attn_kernel, cudaFuncAttributeMaxDynamicSharedMemorySize, ATTN_SMEM_BYTES);

    const int n4x = TT * HID / 4;
    const int n4w = HID * HID / 4;
    dim3 gg(HID / 128, TT / 128);   // (32, 24)

    // 0: all weight splits (one launch, z selects matrix; Wo pre-split here)
    wsplit_kernel<<<dim3((n4w + 255) / 256, 1, 4), 256>>>(Wq, Wk, Wv, Wo);
    // 1: activation split
    split_kernel<<<(n4x + 255) / 256, 256>>>(x, xhi, xlo, n4x);
    // 2,3,4: Q/K/V GEMMs  (ncu capture window lands here)
    gemm3<<<gg, 256, GEMM_SMEM>>>(xhi, xlo, w1hi, w1lo, bq, qp);
    gemm3<<<gg, 256, GEMM_SMEM>>>(xhi, xlo, w2hi, w2lo, bk, kp);
    gemm3<<<gg, 256, GEMM_SMEM>>>(xhi, xlo, w3hi, w3lo, bv, vp);
    // 5: freq table, 6: rope, 7: attention
    init_freq_kernel<<<1, 64>>>();
    rope_kernel<<<(TT * NH * 64 + 255) / 256, 256>>>(pos);
    attn_kernel<<<dim3(16, NH, NBAT), 128, ATTN_SMEM_BYTES>>>(pk, pv, qstart, qlens,
                                                              kvlens, boff);
    // 8: split attention output, 9: O projection
    split_kernel<<<(n4x + 255) / 256, 256>>>(op, xhi, xlo, n4x);
    gemm3<<<gg, 256, GEMM_SMEM>>>(xhi, xlo, w4hi, w4lo, bo, out);
}

// round 7
// speedup vs baseline: 1.4175x; 1.0423x over previous
#include <cuda_runtime.h>
#include <cuda_bf16.h>
#include <cstdint>

#define TT   3072
#define HID  4096
#define NH   32
#define HD   128
#define NBAT 4
#define MAXB 24

// ============================================================================
// helpers (baseline PTX only — no sm_103a-gated features)
// ============================================================================
__device__ __forceinline__ uint32_t smem_to_u32(const void* p) {
    uint32_t a;
    asm("{ .reg .u64 t; cvta.to.shared.u64 t, %1; cvt.u32.u64 %0, t; }" : "=r"(a) : "l"(p));
    return a;
}
__device__ __forceinline__ void cp16(uint32_t dst, const void* src) {
    asm volatile("cp.async.cg.shared.global [%0], [%1], 16;" :: "r"(dst), "l"(src));
}
#define CP_COMMIT() asm volatile("cp.async.commit_group;" ::: "memory")
#define CP_WAIT1()  asm volatile("cp.async.wait_group 1;" ::: "memory")

__device__ __forceinline__ void ldsm4(uint32_t* r, uint32_t addr) {
    asm volatile("ldmatrix.sync.aligned.m8n8.x4.shared.b16 {%0,%1,%2,%3}, [%4];"
        : "=r"(r[0]), "=r"(r[1]), "=r"(r[2]), "=r"(r[3]) : "r"(addr));
}
__device__ __forceinline__ void mma_bf16(float* c, const uint32_t* a, const uint32_t* b) {
    asm volatile("mma.sync.aligned.m16n8k16.row.col.f32.bf16.bf16.f32 "
        "{%0,%1,%2,%3}, {%4,%5,%6,%7}, {%8,%9}, {%0,%1,%2,%3};"
        : "+f"(c[0]), "+f"(c[1]), "+f"(c[2]), "+f"(c[3])
        : "r"(a[0]), "r"(a[1]), "r"(a[2]), "r"(a[3]), "r"(b[0]), "r"(b[1]));
}

// ---- workspace (static device arrays; no allocation) ----
__device__ float g_q[(size_t)TT * HID];
__device__ float g_k[(size_t)TT * HID];
__device__ float g_v[(size_t)TT * HID];
__device__ float g_o[(size_t)TT * HID];
__device__ float g_freq[64];
__device__ __nv_bfloat16 g_xhi[(size_t)TT * HID];
__device__ __nv_bfloat16 g_xlo[(size_t)TT * HID];
__device__ __nv_bfloat16 g_w1hi[(size_t)HID * HID];
__device__ __nv_bfloat16 g_w1lo[(size_t)HID * HID];
__device__ __nv_bfloat16 g_w2hi[(size_t)HID * HID];
__device__ __nv_bfloat16 g_w2lo[(size_t)HID * HID];
__device__ __nv_bfloat16 g_w3hi[(size_t)HID * HID];
__device__ __nv_bfloat16 g_w3lo[(size_t)HID * HID];
__device__ __nv_bfloat16 g_w4hi[(size_t)HID * HID];
__device__ __nv_bfloat16 g_w4lo[(size_t)HID * HID];

__global__ void init_freq_kernel() {
    int i = threadIdx.x;
    if (i < 64) g_freq[i] = (float)exp(-(double)i * (log(10000.0) / 64.0));
}

// ============================================================================
// fp32 -> bf16 hi/lo split
// ============================================================================
__device__ __forceinline__ void split_body(const float* __restrict__ x,
                                           __nv_bfloat16* __restrict__ hi,
                                           __nv_bfloat16* __restrict__ lo, int i)
{
    float4 v = ((const float4*)x)[i];
    float vv[4] = {v.x, v.y, v.z, v.w};
    __nv_bfloat16 h[4], l[4];
#pragma unroll
    for (int j = 0; j < 4; j++) {
        h[j] = __float2bfloat16(vv[j]);
        l[j] = __float2bfloat16(vv[j] - __bfloat162float(h[j]));
    }
    ((__nv_bfloat162*)hi)[2 * i + 0] = __nv_bfloat162(h[0], h[1]);
    ((__nv_bfloat162*)hi)[2 * i + 1] = __nv_bfloat162(h[2], h[3]);
    ((__nv_bfloat162*)lo)[2 * i + 0] = __nv_bfloat162(l[0], l[1]);
    ((__nv_bfloat162*)lo)[2 * i + 1] = __nv_bfloat162(l[2], l[3]);
}

__global__ __launch_bounds__(256) void split_kernel(
    const float* __restrict__ x, __nv_bfloat16* __restrict__ hi,
    __nv_bfloat16* __restrict__ lo, int n4)
{
    int i = blockIdx.x * blockDim.x + threadIdx.x;
    if (i >= n4) return;
    split_body(x, hi, lo, i);
}

// all 4 weight matrices in one launch (blockIdx.z selects)
__global__ __launch_bounds__(256) void wsplit_kernel(
    const float* __restrict__ Wq, const float* __restrict__ Wk,
    const float* __restrict__ Wv, const float* __restrict__ Wo)
{
    int i = blockIdx.x * blockDim.x + threadIdx.x;
    const int n4 = HID * HID / 4;
    if (i >= n4) return;
    int z = blockIdx.z;
    const float* src = (z == 0) ? Wq : (z == 1) ? Wk : (z == 2) ? Wv : Wo;
    __nv_bfloat16* hi = (z == 0) ? g_w1hi : (z == 1) ? g_w2hi : (z == 2) ? g_w3hi : g_w4hi;
    __nv_bfloat16* lo = (z == 0) ? g_w1lo : (z == 1) ? g_w2lo : (z == 2) ? g_w3lo : g_w4lo;
    split_body(src, hi, lo, i);
}

// ============================================================================
// mma.sync GEMM: C[3072,4096] = A @ B^T + bias, 3-term bf16 split.
// CTA 128x128, BK=64, 8 warps (2x4), warp tile 64x32, cp.async 3-stage.
// Single __syncthreads per mainloop iteration:
//   wait(chunk c) -> barrier -> issue chunk c+2 -> commit -> MMA(stage c%3)
// ============================================================================
#define STAGES  3
#define TILE_B  16384
#define STAGE_B (4 * TILE_B)
#define GEMM_SMEM (STAGES * STAGE_B)   // 196608

__global__ __launch_bounds__(256)
void gemm3(const __nv_bfloat16* __restrict__ Ahi, const __nv_bfloat16* __restrict__ Alo,
           const __nv_bfloat16* __restrict__ Bhi, const __nv_bfloat16* __restrict__ Blo,
           const float* __restrict__ bias, float* __restrict__ C)
{
    extern __shared__ char smem[];
    const uint32_t sb = smem_to_u32(smem);
    const int tid = threadIdx.x;
    const int wid = tid >> 5;
    const int lane = tid & 31;
    const int m0 = blockIdx.y << 7;
    const int n0 = blockIdx.x << 7;
    const int wm = wid >> 2;        // 0..1
    const int wn = wid & 3;         // 0..3

    // ---- loader setup: 2 threads per row, 4x16B each, 4 tiles ----
    const int lrow = tid >> 1;              // 0..127
    const int lcb  = (tid & 1) * 4;         // 16B-chunk base 0 or 4
    const uint32_t lrsw = (uint32_t)(lrow & 7) << 4;
    const __nv_bfloat16* gsrc[4];
    gsrc[0] = Ahi + (size_t)(m0 + lrow) * HID + lcb * 8;
    gsrc[1] = Alo + (size_t)(m0 + lrow) * HID + lcb * 8;
    gsrc[2] = Bhi + (size_t)(n0 + lrow) * HID + lcb * 8;
    gsrc[3] = Blo + (size_t)(n0 + lrow) * HID + lcb * 8;
    uint32_t ldst[4][4];
#pragma unroll
    for (int t = 0; t < 4; t++)
#pragma unroll
        for (int j = 0; j < 4; j++)
            ldst[t][j] = t * TILE_B + lrow * 128 + ((uint32_t)((lcb + j) * 16) ^ lrsw);

    // ---- fragment address setup ----
    uint32_t a_off[4], a_sw[4];
#pragma unroll
    for (int mt = 0; mt < 4; mt++) {
        int m = wm * 64 + mt * 16 + (lane & 15);
        a_off[mt] = (uint32_t)m * 128;
        a_sw[mt]  = (uint32_t)(m & 7) << 4;
    }
    const uint32_t ka = (uint32_t)((lane >> 4) << 4);   // 0 | 16
    uint32_t b_off[2], b_sw[2];
#pragma unroll
    for (int p = 0; p < 2; p++) {
        int n = wn * 32 + p * 16 + (lane & 7) + ((lane & 16) >> 1);
        b_off[p] = (uint32_t)n * 128;
        b_sw[p]  = (uint32_t)(n & 7) << 4;
    }
    const uint32_t kb = (uint32_t)((lane & 8) << 1);    // 0 | 16

    float acc[4][4][4];
#pragma unroll
    for (int i = 0; i < 4; i++)
#pragma unroll
        for (int j = 0; j < 4; j++)
#pragma unroll
            for (int k = 0; k < 4; k++) acc[i][j][k] = 0.f;

    // ---- prologue: load chunks 0,1 ----
#pragma unroll
    for (int s = 0; s < 2; s++) {
        uint32_t base = sb + s * STAGE_B;
#pragma unroll
        for (int t = 0; t < 4; t++) {
            const __nv_bfloat16* src = gsrc[t] + s * 64;
#pragma unroll
            for (int j = 0; j < 4; j++)
                cp16(base + ldst[t][j], src + j * 8);
        }
        CP_COMMIT();
    }

    for (int c = 0; c < 64; c++) {
        // chunk c complete (groups 0..c done; <=1 outstanding)
        CP_WAIT1();
        __syncthreads();

        // issue chunk c+2 into stage (c+2)%3 — the stage read at iter c-1,
        // whose readers have all passed the barrier above
        const int ldc = c + 2;
        if (ldc < 64) {
            uint32_t base = sb + (ldc % 3) * STAGE_B;
#pragma unroll
            for (int t = 0; t < 4; t++) {
                const __nv_bfloat16* src = gsrc[t] + ldc * 64;
#pragma unroll
                for (int j = 0; j < 4; j++)
                    cp16(base + ldst[t][j], src + j * 8);
            }
        }
        CP_COMMIT();

        const uint32_t stb = sb + (c % 3) * STAGE_B;
#pragma unroll
        for (int ks = 0; ks < 4; ks++) {
            uint32_t ahi[4][4], alo[4][4];
#pragma unroll
            for (int mt = 0; mt < 4; mt++) {
                uint32_t ko = ((uint32_t)(ks * 32) + ka) ^ a_sw[mt];
                uint32_t ad = stb + a_off[mt] + ko;
                ldsm4(ahi[mt], ad);
                ldsm4(alo[mt], ad + TILE_B);
            }
            uint32_t bhi[2][4], blo[2][4];
#pragma unroll
            for (int p = 0; p < 2; p++) {
                uint32_t ko = ((uint32_t)(ks * 32) + kb) ^ b_sw[p];
                uint32_t bd = stb + 2 * TILE_B + b_off[p] + ko;
                ldsm4(bhi[p], bd);
                ldsm4(blo[p], bd + TILE_B);
            }
#pragma unroll
            for (int mt = 0; mt < 4; mt++)
#pragma unroll
                for (int nt = 0; nt < 4; nt++) {
                    const uint32_t* bh = &bhi[nt >> 1][2 * (nt & 1)];
                    const uint32_t* bl = &blo[nt >> 1][2 * (nt & 1)];
                    mma_bf16(acc[mt][nt], ahi[mt], bh);
                    mma_bf16(acc[mt][nt], ahi[mt], bl);
                    mma_bf16(acc[mt][nt], alo[mt], bh);
                }
        }
    }

    // ---- epilogue: bias add + store ----
#pragma unroll
    for (int mt = 0; mt < 4; mt++) {
#pragma unroll
        for (int nt = 0; nt < 4; nt++) {
            int row = m0 + wm * 64 + mt * 16 + (lane >> 2);
            int col = n0 + wn * 32 + nt * 8 + 2 * (lane & 3);
            float2 bv = *(const float2*)&bias[col];
            float2 v0, v1;
            v0.x = acc[mt][nt][0] + bv.x; v0.y = acc[mt][nt][1] + bv.y;
            v1.x = acc[mt][nt][2] + bv.x; v1.y = acc[mt][nt][3] + bv.y;
            *(float2*)&C[(size_t)row * HID + col]       = v0;
            *(float2*)&C[(size_t)(row + 8) * HID + col] = v1;
        }
    }
}

// ============================================================================
// RoPE on packed q,k in place (angle in f32 like reference, trig in double)
// ============================================================================
__global__ void rope_kernel(const int* __restrict__ pos) {
    int idx = blockIdx.x * blockDim.x + threadIdx.x;
    if (idx >= TT * NH * 64) return;
    int i = idx & 63;
    int h = (idx >> 6) & 31;
    int t = idx >> 11;
    float p = (float)pos[t];
    float ang = p * g_freq[i];
    double ad = (double)ang;
    float c = (float)cos(ad);
    float s = (float)sin(ad);
    size_t base = ((size_t)t * NH + h) * HD;
    float x1 = g_q[base + i], x2 = g_q[base + 64 + i];
    g_q[base + i]      = x1 * c - x2 * s;
    g_q[base + 64 + i] = x2 * c + x1 * s;
    float y1 = g_k[base + i], y2 = g_k[base + 64 + i];
    g_k[base + i]      = y1 * c - y2 * s;
    g_k[base + 64 + i] = y2 * c + y1 * s;
}

// ============================================================================
// Flash attention (fp32), validated in round 1
// ============================================================================
#define ATTN_SMEM_FLOATS (8192 + 8448 + 4224 + 192)
#define ATTN_SMEM_BYTES  (ATTN_SMEM_FLOATS * 4)

__global__ __launch_bounds__(128) void attn_kernel(
    const float* __restrict__ past_k, const float* __restrict__ past_v,
    const int* __restrict__ q_start, const int* __restrict__ q_lens,
    const int* __restrict__ kv_lens, const int* __restrict__ boff)
{
    extern __shared__ float sm[];
    float* Qs   = sm;
    float* KVs  = sm + 8192;
    float* Ps   = KVs + 8448;
    float* mrow = Ps + 4224;
    float* lrow = mrow + 64;
    float* arow = lrow + 64;

    const int b = blockIdx.z, h = blockIdx.y, qt = blockIdx.x;
    const int qlen = q_lens[b];
    if (qt * 64 >= qlen) return;
    const int qs0 = q_start[b];
    const int kvlen = kv_lens[b];
    const int hist = kvlen - qlen;
    const int tid = threadIdx.x;
    const float scale = 0.08838834764831845f;
    const float NEGINF = __int_as_float(0xff800000);

    const int c4 = (tid & 31) << 2;
    const int r0 = tid >> 5;

#pragma unroll
    for (int rr = 0; rr < 16; rr++) {
        int r = r0 + rr * 4;
        int qglob = qt * 64 + r;
        float4 v = make_float4(0.f, 0.f, 0.f, 0.f);
        if (qglob < qlen)
            v = *(const float4*)&g_q[((size_t)(qs0 + qglob) * NH + h) * HD + c4];
        *(float4*)&Qs[r * 128 + c4] = v;
    }
    if (tid < 64) { mrow[tid] = NEGINF; lrow[tid] = 0.f; }
    __syncthreads();

    const int tq = tid >> 3;
    const int tk = tid & 7;

    float o[4][16];
#pragma unroll
    for (int i = 0; i < 4; i++)
#pragma unroll
        for (int j = 0; j < 16; j++) o[i][j] = 0.f;

    const int qhi  = min(qt * 64 + 63, qlen - 1);
    const int nblk = min((kvlen + 63) >> 6, ((hist + qhi) >> 6) + 1);

    for (int kb = 0; kb < nblk; kb++) {
#pragma unroll
        for (int rr = 0; rr < 16; rr++) {
            int r = r0 + rr * 4;
            int p = kb * 64 + r;
            int pc = min(p, kvlen - 1);
            const float* src;
            if (pc < hist) {
                int blk = boff[b * MAXB + (pc >> 6)];
                src = past_k + ((size_t)(blk * 64 + (pc & 63)) * NH + h) * HD;
            } else {
                src = g_k + ((size_t)(qs0 + pc - hist) * NH + h) * HD;
            }
            *(float4*)&KVs[r * 132 + c4] = *(const float4*)&src[c4];
        }
        __syncthreads();

        float s[4][8];
#pragma unroll
        for (int i = 0; i < 4; i++)
#pragma unroll
            for (int m = 0; m < 8; m++) s[i][m] = 0.f;
#pragma unroll 4
        for (int d = 0; d < 128; d += 4) {
            float4 qv[4];
#pragma unroll
            for (int i = 0; i < 4; i++)
                qv[i] = *(const float4*)&Qs[(tq * 4 + i) * 128 + d];
#pragma unroll
            for (int m = 0; m < 8; m++) {
                float4 kv = *(const float4*)&KVs[(tk + 8 * m) * 132 + d];
#pragma unroll
                for (int i = 0; i < 4; i++)
                    s[i][m] += qv[i].x * kv.x + qv[i].y * kv.y + qv[i].z * kv.z + qv[i].w * kv.w;
            }
        }
#pragma unroll
        for (int i = 0; i < 4; i++) {
            int qglob = qt * 64 + tq * 4 + i;
#pragma unroll
            for (int m = 0; m < 8; m++) {
                int kg = kb * 64 + tk + 8 * m;
                float val = (kg <= hist + qglob) ? s[i][m] * scale : NEGINF;
                Ps[(tq * 4 + i) * 66 + tk + 8 * m] = val;
            }
        }
        __syncthreads();

#pragma unroll
        for (int rr = 0; rr < 16; rr++) {
            int r = r0 + rr * 4;
            int p = kb * 64 + r;
            int pc = min(p, kvlen - 1);
            const float* src;
            if (pc < hist) {
                int blk = boff[b * MAXB + (pc >> 6)];
                src = past_v + ((size_t)(blk * 64 + (pc & 63)) * NH + h) * HD;
            } else {
                src = g_v + ((size_t)(qs0 + pc - hist) * NH + h) * HD;
            }
            *(float4*)&KVs[r * 132 + c4] = *(const float4*)&src[c4];
        }

        if (tid < 64) {
            int r = tid;
            float mo = mrow[r];
            float mx = mo;
#pragma unroll 8
            for (int j = 0; j < 64; j++) mx = fmaxf(mx, Ps[r * 66 + j]);
            float alpha = expf(mo - mx);
            float sum = 0.f;
#pragma unroll 8
            for (int j = 0; j < 64; j++) {
                float pj = expf(Ps[r * 66 + j] - mx);
                Ps[r * 66 + j] = pj;
                sum += pj;
            }
            mrow[r] = mx;
            lrow[r] = lrow[r] * alpha + sum;
            arow[r] = alpha;
        }
        __syncthreads();

#pragma unroll
        for (int i = 0; i < 4; i++) {
            float a = arow[tq * 4 + i];
#pragma unroll
            for (int j = 0; j < 16; j++) o[i][j] *= a;
        }
#pragma unroll 2
        for (int k = 0; k < 64; k++) {
            float pr[4];
#pragma unroll
            for (int i = 0; i < 4; i++) pr[i] = Ps[(tq * 4 + i) * 66 + k];
#pragma unroll
            for (int m = 0; m < 4; m++) {
                float4 vv = *(const float4*)&KVs[k * 132 + tk * 4 + 32 * m];
#pragma unroll
                for (int i = 0; i < 4; i++) {
                    o[i][m * 4 + 0] += pr[i] * vv.x;
                    o[i][m * 4 + 1] += pr[i] * vv.y;
                    o[i][m * 4 + 2] += pr[i] * vv.z;
                    o[i][m * 4 + 3] += pr[i] * vv.w;
                }
            }
        }
        __syncthreads();
    }

#pragma unroll
    for (int i = 0; i < 4; i++) {
        int qglob = qt * 64 + tq * 4 + i;
        if (qglob >= qlen) continue;
        float inv = 1.f / lrow[tq * 4 + i];
        size_t base = ((size_t)(qs0 + qglob) * NH + h) * HD;
#pragma unroll
        for (int m = 0; m < 4; m++) {
            float4 w;
            w.x = o[i][m * 4 + 0] * inv;
            w.y = o[i][m * 4 + 1] * inv;
            w.z = o[i][m * 4 + 2] * inv;
            w.w = o[i][m * 4 + 3] * inv;
            *(float4*)&g_o[base + tk * 4 + 32 * m] = w;
        }
    }
}

// ============================================================================
extern "C" void kernel_launch(void* const* d_in, const int* in_sizes, int n_in,
                              void* d_out, int out_size) {
    const float* x      = (const float*)d_in[0];
    const int*   pos    = (const int*)d_in[1];
    const int*   qstart = (const int*)d_in[2];
    const int*   qlens  = (const int*)d_in[3];
    const int*   kvlens = (const int*)d_in[4];
    const int*   boff   = (const int*)d_in[5];
    const float* pk     = (const float*)d_in[6];
    const float* pv     = (const float*)d_in[7];
    const float* Wq = (const float*)d_in[8];
    const float* bq = (const float*)d_in[9];
    const float* Wk = (const float*)d_in[10];
    const float* bk = (const float*)d_in[11];
    const float* Wv = (const float*)d_in[12];
    const float* bv = (const float*)d_in[13];
    const float* Wo = (const float*)d_in[14];
    const float* bo = (const float*)d_in[15];
    float* out = (float*)d_out;

    float *qp, *kp, *vp, *op;
    cudaGetSymbolAddress((void**)&qp, g_q);
    cudaGetSymbolAddress((void**)&kp, g_k);
    cudaGetSymbolAddress((void**)&vp, g_v);
    cudaGetSymbolAddress((void**)&op, g_o);
    __nv_bfloat16 *xhi, *xlo, *w1hi, *w1lo, *w2hi, *w2lo, *w3hi, *w3lo, *w4hi, *w4lo;
    cudaGetSymbolAddress((void**)&xhi, g_xhi);
    cudaGetSymbolAddress((void**)&xlo, g_xlo);
    cudaGetSymbolAddress((void**)&w1hi, g_w1hi);
    cudaGetSymbolAddress((void**)&w1lo, g_w1lo);
    cudaGetSymbolAddress((void**)&w2hi, g_w2hi);
    cudaGetSymbolAddress((void**)&w2lo, g_w2lo);
    cudaGetSymbolAddress((void**)&w3hi, g_w3hi);
    cudaGetSymbolAddress((void**)&w3lo, g_w3lo);
    cudaGetSymbolAddress((void**)&w4hi, g_w4hi);
    cudaGetSymbolAddress((void**)&w4lo, g_w4lo);

    cudaFuncSetAttribute(gemm3, cudaFuncAttributeMaxDynamicSharedMemorySize, GEMM_SMEM);
    cudaFuncSetAttribute(attn_kernel, cudaFuncAttributeMaxDynamicSharedMemorySize, ATTN_SMEM_BYTES);

    const int n4x = TT * HID / 4;
    const int n4w = HID * HID / 4;
    dim3 gg(HID / 128, TT / 128);   // (32, 24)

    // 0: all weight splits (one launch, z selects matrix; Wo pre-split here)
    wsplit_kernel<<<dim3((n4w + 255) / 256, 1, 4), 256>>>(Wq, Wk, Wv, Wo);
    // 1: activation split
    split_kernel<<<(n4x + 255) / 256, 256>>>(x, xhi, xlo, n4x);
    // 2,3,4: Q/K/V GEMMs  (ncu capture window lands here)
    gemm3<<<gg, 256, GEMM_SMEM>>>(xhi, xlo, w1hi, w1lo, bq, qp);
    gemm3<<<gg, 256, GEMM_SMEM>>>(xhi, xlo, w2hi, w2lo, bk, kp);
    gemm3<<<gg, 256, GEMM_SMEM>>>(xhi, xlo, w3hi, w3lo, bv, vp);
    // 5: freq table, 6: rope, 7: attention
    init_freq_kernel<<<1, 64>>>();
    rope_kernel<<<(TT * NH * 64 + 255) / 256, 256>>>(pos);
    attn_kernel<<<dim3(16, NH, NBAT), 128, ATTN_SMEM_BYTES>>>(pk, pv, qstart, qlens,
                                                              kvlens, boff);
    // 8: split attention output, 9: O projection
    split_kernel<<<(n4x + 255) / 256, 256>>>(op, xhi, xlo, n4x);
    gemm3<<<gg, 256, GEMM_SMEM>>>(xhi, xlo, w4hi, w4lo, bo, out);
}

// round 8
// speedup vs baseline: 1.5358x; 1.0834x over previous
#include <cuda_runtime.h>
#include <cuda_bf16.h>
#include <cuda_fp16.h>
#include <cstdint>

#define TT   3072
#define HID  4096
#define NH   32
#define HD   128
#define NBAT 4
#define MAXB 24

// ============================================================================
// helpers (baseline PTX only — no sm_103a-gated features)
// ============================================================================
__device__ __forceinline__ uint32_t smem_to_u32(const void* p) {
    uint32_t a;
    asm("{ .reg .u64 t; cvta.to.shared.u64 t, %1; cvt.u32.u64 %0, t; }" : "=r"(a) : "l"(p));
    return a;
}
__device__ __forceinline__ void cp16(uint32_t dst, const void* src) {
    asm volatile("cp.async.cg.shared.global [%0], [%1], 16;" :: "r"(dst), "l"(src));
}
#define CP_COMMIT() asm volatile("cp.async.commit_group;" ::: "memory")
#define CP_WAIT1()  asm volatile("cp.async.wait_group 1;" ::: "memory")

__device__ __forceinline__ void ldsm4(uint32_t* r, uint32_t addr) {
    asm volatile("ldmatrix.sync.aligned.m8n8.x4.shared.b16 {%0,%1,%2,%3}, [%4];"
        : "=r"(r[0]), "=r"(r[1]), "=r"(r[2]), "=r"(r[3]) : "r"(addr));
}
__device__ __forceinline__ void mma_bf16(float* c, const uint32_t* a, const uint32_t* b) {
    asm volatile("mma.sync.aligned.m16n8k16.row.col.f32.bf16.bf16.f32 "
        "{%0,%1,%2,%3}, {%4,%5,%6,%7}, {%8,%9}, {%0,%1,%2,%3};"
        : "+f"(c[0]), "+f"(c[1]), "+f"(c[2]), "+f"(c[3])
        : "r"(a[0]), "r"(a[1]), "r"(a[2]), "r"(a[3]), "r"(b[0]), "r"(b[1]));
}
__device__ __forceinline__ void mma_fp16(float* c, const uint32_t* a, const uint32_t* b) {
    asm volatile("mma.sync.aligned.m16n8k16.row.col.f32.f16.f16.f32 "
        "{%0,%1,%2,%3}, {%4,%5,%6,%7}, {%8,%9}, {%0,%1,%2,%3};"
        : "+f"(c[0]), "+f"(c[1]), "+f"(c[2]), "+f"(c[3])
        : "r"(a[0]), "r"(a[1]), "r"(a[2]), "r"(a[3]), "r"(b[0]), "r"(b[1]));
}

// ---- workspace (static device arrays; no allocation) ----
__device__ float g_q[(size_t)TT * HID];
__device__ float g_k[(size_t)TT * HID];
__device__ float g_v[(size_t)TT * HID];
__device__ float g_o[(size_t)TT * HID];
__device__ float g_freq[64];
__device__ __nv_bfloat16 g_xhi[(size_t)TT * HID];
__device__ __nv_bfloat16 g_xlo[(size_t)TT * HID];
__device__ __half        g_xh [(size_t)TT * HID];
__device__ __nv_bfloat16 g_w1hi[(size_t)HID * HID];
__device__ __nv_bfloat16 g_w1lo[(size_t)HID * HID];
__device__ __nv_bfloat16 g_w2hi[(size_t)HID * HID];
__device__ __nv_bfloat16 g_w2lo[(size_t)HID * HID];
__device__ __half        g_w3h [(size_t)HID * HID];
__device__ __half        g_w3l [(size_t)HID * HID];
__device__ __half        g_w4h [(size_t)HID * HID];
__device__ __half        g_w4l [(size_t)HID * HID];

__global__ void init_freq_kernel() {
    int i = threadIdx.x;
    if (i < 64) g_freq[i] = (float)exp(-(double)i * (log(10000.0) / 64.0));
}

// ============================================================================
// splits
// ============================================================================
__device__ __forceinline__ void split_bf16(const float* __restrict__ x,
                                           __nv_bfloat16* __restrict__ hi,
                                           __nv_bfloat16* __restrict__ lo, int i)
{
    float4 v = ((const float4*)x)[i];
    float vv[4] = {v.x, v.y, v.z, v.w};
    __nv_bfloat16 h[4], l[4];
#pragma unroll
    for (int j = 0; j < 4; j++) {
        h[j] = __float2bfloat16(vv[j]);
        l[j] = __float2bfloat16(vv[j] - __bfloat162float(h[j]));
    }
    ((__nv_bfloat162*)hi)[2 * i + 0] = __nv_bfloat162(h[0], h[1]);
    ((__nv_bfloat162*)hi)[2 * i + 1] = __nv_bfloat162(h[2], h[3]);
    ((__nv_bfloat162*)lo)[2 * i + 0] = __nv_bfloat162(l[0], l[1]);
    ((__nv_bfloat162*)lo)[2 * i + 1] = __nv_bfloat162(l[2], l[3]);
}
__device__ __forceinline__ void split_fp16(const float* __restrict__ x,
                                           __half* __restrict__ hi,
                                           __half* __restrict__ lo, int i)
{
    float4 v = ((const float4*)x)[i];
    float vv[4] = {v.x, v.y, v.z, v.w};
    __half h[4], l[4];
#pragma unroll
    for (int j = 0; j < 4; j++) {
        h[j] = __float2half(vv[j]);
        l[j] = __float2half(vv[j] - __half2float(h[j]));
    }
    ((__half2*)hi)[2 * i + 0] = __half2(h[0], h[1]);
    ((__half2*)hi)[2 * i + 1] = __half2(h[2], h[3]);
    ((__half2*)lo)[2 * i + 0] = __half2(l[0], l[1]);
    ((__half2*)lo)[2 * i + 1] = __half2(l[2], l[3]);
}

// x -> bf16 hi/lo (for Q,K GEMMs) + fp16 single (for V GEMM), one pass
__global__ __launch_bounds__(256) void xsplit3_kernel(const float* __restrict__ x, int n4)
{
    int i = blockIdx.x * blockDim.x + threadIdx.x;
    if (i >= n4) return;
    float4 v = ((const float4*)x)[i];
    float vv[4] = {v.x, v.y, v.z, v.w};
    __nv_bfloat16 h[4], l[4];
    __half f[4];
#pragma unroll
    for (int j = 0; j < 4; j++) {
        h[j] = __float2bfloat16(vv[j]);
        l[j] = __float2bfloat16(vv[j] - __bfloat162float(h[j]));
        f[j] = __float2half(vv[j]);
    }
    ((__nv_bfloat162*)g_xhi)[2 * i + 0] = __nv_bfloat162(h[0], h[1]);
    ((__nv_bfloat162*)g_xhi)[2 * i + 1] = __nv_bfloat162(h[2], h[3]);
    ((__nv_bfloat162*)g_xlo)[2 * i + 0] = __nv_bfloat162(l[0], l[1]);
    ((__nv_bfloat162*)g_xlo)[2 * i + 1] = __nv_bfloat162(l[2], l[3]);
    ((__half2*)g_xh)[2 * i + 0] = __half2(f[0], f[1]);
    ((__half2*)g_xh)[2 * i + 1] = __half2(f[2], f[3]);
}

// attention output -> fp16 single (for O GEMM)
__global__ __launch_bounds__(256) void osplit_kernel(int n4)
{
    int i = blockIdx.x * blockDim.x + threadIdx.x;
    if (i >= n4) return;
    float4 v = ((const float4*)g_o)[i];
    ((__half2*)g_xh)[2 * i + 0] = __half2(__float2half(v.x), __float2half(v.y));
    ((__half2*)g_xh)[2 * i + 1] = __half2(__float2half(v.z), __float2half(v.w));
}

// all 4 weight matrices in one launch (blockIdx.z selects); Wq/Wk bf16, Wv/Wo fp16
__global__ __launch_bounds__(256) void wsplit_kernel(
    const float* __restrict__ Wq, const float* __restrict__ Wk,
    const float* __restrict__ Wv, const float* __restrict__ Wo)
{
    int i = blockIdx.x * blockDim.x + threadIdx.x;
    const int n4 = HID * HID / 4;
    if (i >= n4) return;
    int z = blockIdx.z;
    if (z == 0)      split_bf16(Wq, g_w1hi, g_w1lo, i);
    else if (z == 1) split_bf16(Wk, g_w2hi, g_w2lo, i);
    else if (z == 2) split_fp16(Wv, g_w3h, g_w3l, i);
    else             split_fp16(Wo, g_w4h, g_w4l, i);
}

// ============================================================================
// GEMM common geometry: CTA 128x128, BK=64, 8 warps (2x4), warp tile 64x32,
// cp.async 3-stage, single __syncthreads per iteration (R7 pipeline).
// ============================================================================
#define TILE_B  16384

// ---- bf16 3-term kernel (Q,K): stage = 4 tiles (Ahi,Alo,Bhi,Blo) ----
#define STAGE3_B (4 * TILE_B)
#define GEMM3_SMEM (3 * STAGE3_B)   // 196608

__global__ __launch_bounds__(256)
void gemm3(const __nv_bfloat16* __restrict__ Ahi, const __nv_bfloat16* __restrict__ Alo,
           const __nv_bfloat16* __restrict__ Bhi, const __nv_bfloat16* __restrict__ Blo,
           const float* __restrict__ bias, float* __restrict__ C)
{
    extern __shared__ char smem[];
    const uint32_t sb = smem_to_u32(smem);
    const int tid = threadIdx.x;
    const int wid = tid >> 5;
    const int lane = tid & 31;
    const int m0 = blockIdx.y << 7;
    const int n0 = blockIdx.x << 7;
    const int wm = wid >> 2;
    const int wn = wid & 3;

    const int lrow = tid >> 1;
    const int lcb  = (tid & 1) * 4;
    const uint32_t lrsw = (uint32_t)(lrow & 7) << 4;
    const __nv_bfloat16* gsrc[4];
    gsrc[0] = Ahi + (size_t)(m0 + lrow) * HID + lcb * 8;
    gsrc[1] = Alo + (size_t)(m0 + lrow) * HID + lcb * 8;
    gsrc[2] = Bhi + (size_t)(n0 + lrow) * HID + lcb * 8;
    gsrc[3] = Blo + (size_t)(n0 + lrow) * HID + lcb * 8;
    uint32_t ldst[4][4];
#pragma unroll
    for (int t = 0; t < 4; t++)
#pragma unroll
        for (int j = 0; j < 4; j++)
            ldst[t][j] = t * TILE_B + lrow * 128 + ((uint32_t)((lcb + j) * 16) ^ lrsw);

    uint32_t a_off[4], a_sw[4];
#pragma unroll
    for (int mt = 0; mt < 4; mt++) {
        int m = wm * 64 + mt * 16 + (lane & 15);
        a_off[mt] = (uint32_t)m * 128;
        a_sw[mt]  = (uint32_t)(m & 7) << 4;
    }
    const uint32_t ka = (uint32_t)((lane >> 4) << 4);
    uint32_t b_off[2], b_sw[2];
#pragma unroll
    for (int p = 0; p < 2; p++) {
        int n = wn * 32 + p * 16 + (lane & 7) + ((lane & 16) >> 1);
        b_off[p] = (uint32_t)n * 128;
        b_sw[p]  = (uint32_t)(n & 7) << 4;
    }
    const uint32_t kb = (uint32_t)((lane & 8) << 1);

    float acc[4][4][4];
#pragma unroll
    for (int i = 0; i < 4; i++)
#pragma unroll
        for (int j = 0; j < 4; j++)
#pragma unroll
            for (int k = 0; k < 4; k++) acc[i][j][k] = 0.f;

#pragma unroll
    for (int s = 0; s < 2; s++) {
        uint32_t base = sb + s * STAGE3_B;
#pragma unroll
        for (int t = 0; t < 4; t++) {
            const __nv_bfloat16* src = gsrc[t] + s * 64;
#pragma unroll
            for (int j = 0; j < 4; j++)
                cp16(base + ldst[t][j], src + j * 8);
        }
        CP_COMMIT();
    }

    for (int c = 0; c < 64; c++) {
        CP_WAIT1();
        __syncthreads();
        const int ldc = c + 2;
        if (ldc < 64) {
            uint32_t base = sb + (ldc % 3) * STAGE3_B;
#pragma unroll
            for (int t = 0; t < 4; t++) {
                const __nv_bfloat16* src = gsrc[t] + ldc * 64;
#pragma unroll
                for (int j = 0; j < 4; j++)
                    cp16(base + ldst[t][j], src + j * 8);
            }
        }
        CP_COMMIT();

        const uint32_t stb = sb + (c % 3) * STAGE3_B;
#pragma unroll
        for (int ks = 0; ks < 4; ks++) {
            uint32_t ahi[4][4], alo[4][4];
#pragma unroll
            for (int mt = 0; mt < 4; mt++) {
                uint32_t ko = ((uint32_t)(ks * 32) + ka) ^ a_sw[mt];
                uint32_t ad = stb + a_off[mt] + ko;
                ldsm4(ahi[mt], ad);
                ldsm4(alo[mt], ad + TILE_B);
            }
            uint32_t bhi[2][4], blo[2][4];
#pragma unroll
            for (int p = 0; p < 2; p++) {
                uint32_t ko = ((uint32_t)(ks * 32) + kb) ^ b_sw[p];
                uint32_t bd = stb + 2 * TILE_B + b_off[p] + ko;
                ldsm4(bhi[p], bd);
                ldsm4(blo[p], bd + TILE_B);
            }
#pragma unroll
            for (int mt = 0; mt < 4; mt++)
#pragma unroll
                for (int nt = 0; nt < 4; nt++) {
                    const uint32_t* bh = &bhi[nt >> 1][2 * (nt & 1)];
                    const uint32_t* bl = &blo[nt >> 1][2 * (nt & 1)];
                    mma_bf16(acc[mt][nt], ahi[mt], bh);
                    mma_bf16(acc[mt][nt], ahi[mt], bl);
                    mma_bf16(acc[mt][nt], alo[mt], bh);
                }
        }
    }

#pragma unroll
    for (int mt = 0; mt < 4; mt++) {
#pragma unroll
        for (int nt = 0; nt < 4; nt++) {
            int row = m0 + wm * 64 + mt * 16 + (lane >> 2);
            int col = n0 + wn * 32 + nt * 8 + 2 * (lane & 3);
            float2 bv = *(const float2*)&bias[col];
            float2 v0, v1;
            v0.x = acc[mt][nt][0] + bv.x; v0.y = acc[mt][nt][1] + bv.y;
            v1.x = acc[mt][nt][2] + bv.x; v1.y = acc[mt][nt][3] + bv.y;
            *(float2*)&C[(size_t)row * HID + col]       = v0;
            *(float2*)&C[(size_t)(row + 8) * HID + col] = v1;
        }
    }
}

// ---- fp16 2-term kernel (V,O): A single fp16, B hi/lo pair; stage = 3 tiles ----
#define STAGE2_B (3 * TILE_B)
#define GEMM2_SMEM (3 * STAGE2_B)   // 147456

__global__ __launch_bounds__(256)
void gemm2h(const __half* __restrict__ A, const __half* __restrict__ Bh,
            const __half* __restrict__ Bl,
            const float* __restrict__ bias, float* __restrict__ C)
{
    extern __shared__ char smem[];
    const uint32_t sb = smem_to_u32(smem);
    const int tid = threadIdx.x;
    const int wid = tid >> 5;
    const int lane = tid & 31;
    const int m0 = blockIdx.y << 7;
    const int n0 = blockIdx.x << 7;
    const int wm = wid >> 2;
    const int wn = wid & 3;

    const int lrow = tid >> 1;
    const int lcb  = (tid & 1) * 4;
    const uint32_t lrsw = (uint32_t)(lrow & 7) << 4;
    const __half* gsrc[3];
    gsrc[0] = A  + (size_t)(m0 + lrow) * HID + lcb * 8;
    gsrc[1] = Bh + (size_t)(n0 + lrow) * HID + lcb * 8;
    gsrc[2] = Bl + (size_t)(n0 + lrow) * HID + lcb * 8;
    uint32_t ldst[3][4];
#pragma unroll
    for (int t = 0; t < 3; t++)
#pragma unroll
        for (int j = 0; j < 4; j++)
            ldst[t][j] = t * TILE_B + lrow * 128 + ((uint32_t)((lcb + j) * 16) ^ lrsw);

    uint32_t a_off[4], a_sw[4];
#pragma unroll
    for (int mt = 0; mt < 4; mt++) {
        int m = wm * 64 + mt * 16 + (lane & 15);
        a_off[mt] = (uint32_t)m * 128;
        a_sw[mt]  = (uint32_t)(m & 7) << 4;
    }
    const uint32_t ka = (uint32_t)((lane >> 4) << 4);
    uint32_t b_off[2], b_sw[2];
#pragma unroll
    for (int p = 0; p < 2; p++) {
        int n = wn * 32 + p * 16 + (lane & 7) + ((lane & 16) >> 1);
        b_off[p] = (uint32_t)n * 128;
        b_sw[p]  = (uint32_t)(n & 7) << 4;
    }
    const uint32_t kb = (uint32_t)((lane & 8) << 1);

    float acc[4][4][4];
#pragma unroll
    for (int i = 0; i < 4; i++)
#pragma unroll
        for (int j = 0; j < 4; j++)
#pragma unroll
            for (int k = 0; k < 4; k++) acc[i][j][k] = 0.f;

#pragma unroll
    for (int s = 0; s < 2; s++) {
        uint32_t base = sb + s * STAGE2_B;
#pragma unroll
        for (int t = 0; t < 3; t++) {
            const __half* src = gsrc[t] + s * 64;
#pragma unroll
            for (int j = 0; j < 4; j++)
                cp16(base + ldst[t][j], src + j * 8);
        }
        CP_COMMIT();
    }

    for (int c = 0; c < 64; c++) {
        CP_WAIT1();
        __syncthreads();
        const int ldc = c + 2;
        if (ldc < 64) {
            uint32_t base = sb + (ldc % 3) * STAGE2_B;
#pragma unroll
            for (int t = 0; t < 3; t++) {
                const __half* src = gsrc[t] + ldc * 64;
#pragma unroll
                for (int j = 0; j < 4; j++)
                    cp16(base + ldst[t][j], src + j * 8);
            }
        }
        CP_COMMIT();

        const uint32_t stb = sb + (c % 3) * STAGE2_B;
#pragma unroll
        for (int ks = 0; ks < 4; ks++) {
            uint32_t af[4][4];
#pragma unroll
            for (int mt = 0; mt < 4; mt++) {
                uint32_t ko = ((uint32_t)(ks * 32) + ka) ^ a_sw[mt];
                ldsm4(af[mt], stb + a_off[mt] + ko);
            }
            uint32_t bhf[2][4], blf[2][4];
#pragma unroll
            for (int p = 0; p < 2; p++) {
                uint32_t ko = ((uint32_t)(ks * 32) + kb) ^ b_sw[p];
                uint32_t bd = stb + TILE_B + b_off[p] + ko;
                ldsm4(bhf[p], bd);
                ldsm4(blf[p], bd + TILE_B);
            }
#pragma unroll
            for (int mt = 0; mt < 4; mt++)
#pragma unroll
                for (int nt = 0; nt < 4; nt++) {
                    const uint32_t* bh = &bhf[nt >> 1][2 * (nt & 1)];
                    const uint32_t* bl = &blf[nt >> 1][2 * (nt & 1)];
                    mma_fp16(acc[mt][nt], af[mt], bh);
                    mma_fp16(acc[mt][nt], af[mt], bl);
                }
        }
    }

#pragma unroll
    for (int mt = 0; mt < 4; mt++) {
#pragma unroll
        for (int nt = 0; nt < 4; nt++) {
            int row = m0 + wm * 64 + mt * 16 + (lane >> 2);
            int col = n0 + wn * 32 + nt * 8 + 2 * (lane & 3);
            float2 bv = *(const float2*)&bias[col];
            float2 v0, v1;
            v0.x = acc[mt][nt][0] + bv.x; v0.y = acc[mt][nt][1] + bv.y;
            v1.x = acc[mt][nt][2] + bv.x; v1.y = acc[mt][nt][3] + bv.y;
            *(float2*)&C[(size_t)row * HID + col]       = v0;
            *(float2*)&C[(size_t)(row + 8) * HID + col] = v1;
        }
    }
}

// ============================================================================
// RoPE on packed q,k in place (angle in f32 like reference, trig in double)
// ============================================================================
__global__ void rope_kernel(const int* __restrict__ pos) {
    int idx = blockIdx.x * blockDim.x + threadIdx.x;
    if (idx >= TT * NH * 64) return;
    int i = idx & 63;
    int h = (idx >> 6) & 31;
    int t = idx >> 11;
    float p = (float)pos[t];
    float ang = p * g_freq[i];
    double ad = (double)ang;
    float c = (float)cos(ad);
    float s = (float)sin(ad);
    size_t base = ((size_t)t * NH + h) * HD;
    float x1 = g_q[base + i], x2 = g_q[base + 64 + i];
    g_q[base + i]      = x1 * c - x2 * s;
    g_q[base + 64 + i] = x2 * c + x1 * s;
    float y1 = g_k[base + i], y2 = g_k[base + 64 + i];
    g_k[base + i]      = y1 * c - y2 * s;
    g_k[base + 64 + i] = y2 * c + y1 * s;
}

// ============================================================================
// Flash attention (fp32), validated in round 1
// ============================================================================
#define ATTN_SMEM_FLOATS (8192 + 8448 + 4224 + 192)
#define ATTN_SMEM_BYTES  (ATTN_SMEM_FLOATS * 4)

__global__ __launch_bounds__(128) void attn_kernel(
    const float* __restrict__ past_k, const float* __restrict__ past_v,
    const int* __restrict__ q_start, const int* __restrict__ q_lens,
    const int* __restrict__ kv_lens, const int* __restrict__ boff)
{
    extern __shared__ float sm[];
    float* Qs   = sm;
    float* KVs  = sm + 8192;
    float* Ps   = KVs + 8448;
    float* mrow = Ps + 4224;
    float* lrow = mrow + 64;
    float* arow = lrow + 64;

    const int b = blockIdx.z, h = blockIdx.y, qt = blockIdx.x;
    const int qlen = q_lens[b];
    if (qt * 64 >= qlen) return;
    const int qs0 = q_start[b];
    const int kvlen = kv_lens[b];
    const int hist = kvlen - qlen;
    const int tid = threadIdx.x;
    const float scale = 0.08838834764831845f;
    const float NEGINF = __int_as_float(0xff800000);

    const int c4 = (tid & 31) << 2;
    const int r0 = tid >> 5;

#pragma unroll
    for (int rr = 0; rr < 16; rr++) {
        int r = r0 + rr * 4;
        int qglob = qt * 64 + r;
        float4 v = make_float4(0.f, 0.f, 0.f, 0.f);
        if (qglob < qlen)
            v = *(const float4*)&g_q[((size_t)(qs0 + qglob) * NH + h) * HD + c4];
        *(float4*)&Qs[r * 128 + c4] = v;
    }
    if (tid < 64) { mrow[tid] = NEGINF; lrow[tid] = 0.f; }
    __syncthreads();

    const int tq = tid >> 3;
    const int tk = tid & 7;

    float o[4][16];
#pragma unroll
    for (int i = 0; i < 4; i++)
#pragma unroll
        for (int j = 0; j < 16; j++) o[i][j] = 0.f;

    const int qhi  = min(qt * 64 + 63, qlen - 1);
    const int nblk = min((kvlen + 63) >> 6, ((hist + qhi) >> 6) + 1);

    for (int kb = 0; kb < nblk; kb++) {
#pragma unroll
        for (int rr = 0; rr < 16; rr++) {
            int r = r0 + rr * 4;
            int p = kb * 64 + r;
            int pc = min(p, kvlen - 1);
            const float* src;
            if (pc < hist) {
                int blk = boff[b * MAXB + (pc >> 6)];
                src = past_k + ((size_t)(blk * 64 + (pc & 63)) * NH + h) * HD;
            } else {
                src = g_k + ((size_t)(qs0 + pc - hist) * NH + h) * HD;
            }
            *(float4*)&KVs[r * 132 + c4] = *(const float4*)&src[c4];
        }
        __syncthreads();

        float s[4][8];
#pragma unroll
        for (int i = 0; i < 4; i++)
#pragma unroll
            for (int m = 0; m < 8; m++) s[i][m] = 0.f;
#pragma unroll 4
        for (int d = 0; d < 128; d += 4) {
            float4 qv[4];
#pragma unroll
            for (int i = 0; i < 4; i++)
                qv[i] = *(const float4*)&Qs[(tq * 4 + i) * 128 + d];
#pragma unroll
            for (int m = 0; m < 8; m++) {
                float4 kv = *(const float4*)&KVs[(tk + 8 * m) * 132 + d];
#pragma unroll
                for (int i = 0; i < 4; i++)
                    s[i][m] += qv[i].x * kv.x + qv[i].y * kv.y + qv[i].z * kv.z + qv[i].w * kv.w;
            }
        }
#pragma unroll
        for (int i = 0; i < 4; i++) {
            int qglob = qt * 64 + tq * 4 + i;
#pragma unroll
            for (int m = 0; m < 8; m++) {
                int kg = kb * 64 + tk + 8 * m;
                float val = (kg <= hist + qglob) ? s[i][m] * scale : NEGINF;
                Ps[(tq * 4 + i) * 66 + tk + 8 * m] = val;
            }
        }
        __syncthreads();

#pragma unroll
        for (int rr = 0; rr < 16; rr++) {
            int r = r0 + rr * 4;
            int p = kb * 64 + r;
            int pc = min(p, kvlen - 1);
            const float* src;
            if (pc < hist) {
                int blk = boff[b * MAXB + (pc >> 6)];
                src = past_v + ((size_t)(blk * 64 + (pc & 63)) * NH + h) * HD;
            } else {
                src = g_v + ((size_t)(qs0 + pc - hist) * NH + h) * HD;
            }
            *(float4*)&KVs[r * 132 + c4] = *(const float4*)&src[c4];
        }

        if (tid < 64) {
            int r = tid;
            float mo = mrow[r];
            float mx = mo;
#pragma unroll 8
            for (int j = 0; j < 64; j++) mx = fmaxf(mx, Ps[r * 66 + j]);
            float alpha = expf(mo - mx);
            float sum = 0.f;
#pragma unroll 8
            for (int j = 0; j < 64; j++) {
                float pj = expf(Ps[r * 66 + j] - mx);
                Ps[r * 66 + j] = pj;
                sum += pj;
            }
            mrow[r] = mx;
            lrow[r] = lrow[r] * alpha + sum;
            arow[r] = alpha;
        }
        __syncthreads();

#pragma unroll
        for (int i = 0; i < 4; i++) {
            float a = arow[tq * 4 + i];
#pragma unroll
            for (int j = 0; j < 16; j++) o[i][j] *= a;
        }
#pragma unroll 2
        for (int k = 0; k < 64; k++) {
            float pr[4];
#pragma unroll
            for (int i = 0; i < 4; i++) pr[i] = Ps[(tq * 4 + i) * 66 + k];
#pragma unroll
            for (int m = 0; m < 4; m++) {
                float4 vv = *(const float4*)&KVs[k * 132 + tk * 4 + 32 * m];
#pragma unroll
                for (int i = 0; i < 4; i++) {
                    o[i][m * 4 + 0] += pr[i] * vv.x;
                    o[i][m * 4 + 1] += pr[i] * vv.y;
                    o[i][m * 4 + 2] += pr[i] * vv.z;
                    o[i][m * 4 + 3] += pr[i] * vv.w;
                }
            }
        }
        __syncthreads();
    }

#pragma unroll
    for (int i = 0; i < 4; i++) {
        int qglob = qt * 64 + tq * 4 + i;
        if (qglob >= qlen) continue;
        float inv = 1.f / lrow[tq * 4 + i];
        size_t base = ((size_t)(qs0 + qglob) * NH + h) * HD;
#pragma unroll
        for (int m = 0; m < 4; m++) {
            float4 w;
            w.x = o[i][m * 4 + 0] * inv;
            w.y = o[i][m * 4 + 1] * inv;
            w.z = o[i][m * 4 + 2] * inv;
            w.w = o[i][m * 4 + 3] * inv;
            *(float4*)&g_o[base + tk * 4 + 32 * m] = w;
        }
    }
}

// ============================================================================
extern "C" void kernel_launch(void* const* d_in, const int* in_sizes, int n_in,
                              void* d_out, int out_size) {
    const float* x      = (const float*)d_in[0];
    const int*   pos    = (const int*)d_in[1];
    const int*   qstart = (const int*)d_in[2];
    const int*   qlens  = (const int*)d_in[3];
    const int*   kvlens = (const int*)d_in[4];
    const int*   boff   = (const int*)d_in[5];
    const float* pk     = (const float*)d_in[6];
    const float* pv     = (const float*)d_in[7];
    const float* Wq = (const float*)d_in[8];
    const float* bq = (const float*)d_in[9];
    const float* Wk = (const float*)d_in[10];
    const float* bk = (const float*)d_in[11];
    const float* Wv = (const float*)d_in[12];
    const float* bv = (const float*)d_in[13];
    const float* Wo = (const float*)d_in[14];
    const float* bo = (const float*)d_in[15];
    float* out = (float*)d_out;

    float *qp, *kp, *vp;
    cudaGetSymbolAddress((void**)&qp, g_q);
    cudaGetSymbolAddress((void**)&kp, g_k);
    cudaGetSymbolAddress((void**)&vp, g_v);
    __nv_bfloat16 *xhi, *xlo, *w1hi, *w1lo, *w2hi, *w2lo;
    __half *xh, *w3h, *w3l, *w4h, *w4l;
    cudaGetSymbolAddress((void**)&xhi, g_xhi);
    cudaGetSymbolAddress((void**)&xlo, g_xlo);
    cudaGetSymbolAddress((void**)&xh,  g_xh);
    cudaGetSymbolAddress((void**)&w1hi, g_w1hi);
    cudaGetSymbolAddress((void**)&w1lo, g_w1lo);
    cudaGetSymbolAddress((void**)&w2hi, g_w2hi);
    cudaGetSymbolAddress((void**)&w2lo, g_w2lo);
    cudaGetSymbolAddress((void**)&w3h, g_w3h);
    cudaGetSymbolAddress((void**)&w3l, g_w3l);
    cudaGetSymbolAddress((void**)&w4h, g_w4h);
    cudaGetSymbolAddress((void**)&w4l, g_w4l);

    cudaFuncSetAttribute(gemm3,  cudaFuncAttributeMaxDynamicSharedMemorySize, GEMM3_SMEM);
    cudaFuncSetAttribute(gemm2h, cudaFuncAttributeMaxDynamicSharedMemorySize, GEMM2_SMEM);
    cudaFuncSetAttribute(attn_kernel, cudaFuncAttributeMaxDynamicSharedMemorySize, ATTN_SMEM_BYTES);

    const int n4x = TT * HID / 4;
    const int n4w = HID * HID / 4;
    dim3 gg(HID / 128, TT / 128);   // (32, 24)

    // 0: weight splits, 1: activation split (bf16 pair + fp16)
    wsplit_kernel<<<dim3((n4w + 255) / 256, 1, 4), 256>>>(Wq, Wk, Wv, Wo);
    xsplit3_kernel<<<(n4x + 255) / 256, 256>>>(x, n4x);
    // 2,3: Q/K GEMMs (bf16 3-term), 4: V GEMM (fp16 2-term)
    gemm3<<<gg, 256, GEMM3_SMEM>>>(xhi, xlo, w1hi, w1lo, bq, qp);
    gemm3<<<gg, 256, GEMM3_SMEM>>>(xhi, xlo, w2hi, w2lo, bk, kp);
    gemm2h<<<gg, 256, GEMM2_SMEM>>>(xh, w3h, w3l, bv, vp);
    // 5: freq, 6: rope, 7: attention
    init_freq_kernel<<<1, 64>>>();
    rope_kernel<<<(TT * NH * 64 + 255) / 256, 256>>>(pos);
    attn_kernel<<<dim3(16, NH, NBAT), 128, ATTN_SMEM_BYTES>>>(pk, pv, qstart, qlens,
                                                              kvlens, boff);
    // 8: attention output -> fp16, 9: O GEMM (fp16 2-term)
    osplit_kernel<<<(n4x + 255) / 256, 256>>>(n4x);
    gemm2h<<<gg, 256, GEMM2_SMEM>>>(xh, w4h, w4l, bo, out);
}

// round 9
// speedup vs baseline: 1.8155x; 1.1821x over previous
#include <cuda_runtime.h>
#include <cuda_bf16.h>
#include <cuda_fp16.h>
#include <cstdint>

#define TT   3072
#define HID  4096
#define NH   32
#define HD   128
#define NBAT 4
#define MAXB 24

// ============================================================================
// helpers (baseline PTX only — no sm_103a-gated features)
// ============================================================================
__device__ __forceinline__ uint32_t smem_to_u32(const void* p) {
    uint32_t a;
    asm("{ .reg .u64 t; cvta.to.shared.u64 t, %1; cvt.u32.u64 %0, t; }" : "=r"(a) : "l"(p));
    return a;
}
__device__ __forceinline__ void cp16(uint32_t dst, const void* src) {
    asm volatile("cp.async.cg.shared.global [%0], [%1], 16;" :: "r"(dst), "l"(src));
}
#define CP_COMMIT() asm volatile("cp.async.commit_group;" ::: "memory")
#define CP_WAIT1()  asm volatile("cp.async.wait_group 1;" ::: "memory")

__device__ __forceinline__ void ldsm4(uint32_t* r, uint32_t addr) {
    asm volatile("ldmatrix.sync.aligned.m8n8.x4.shared.b16 {%0,%1,%2,%3}, [%4];"
        : "=r"(r[0]), "=r"(r[1]), "=r"(r[2]), "=r"(r[3]) : "r"(addr));
}
__device__ __forceinline__ void mma_bf16(float* c, const uint32_t* a, const uint32_t* b) {
    asm volatile("mma.sync.aligned.m16n8k16.row.col.f32.bf16.bf16.f32 "
        "{%0,%1,%2,%3}, {%4,%5,%6,%7}, {%8,%9}, {%0,%1,%2,%3};"
        : "+f"(c[0]), "+f"(c[1]), "+f"(c[2]), "+f"(c[3])
        : "r"(a[0]), "r"(a[1]), "r"(a[2]), "r"(a[3]), "r"(b[0]), "r"(b[1]));
}
__device__ __forceinline__ void mma_fp16(float* c, const uint32_t* a, const uint32_t* b) {
    asm volatile("mma.sync.aligned.m16n8k16.row.col.f32.f16.f16.f32 "
        "{%0,%1,%2,%3}, {%4,%5,%6,%7}, {%8,%9}, {%0,%1,%2,%3};"
        : "+f"(c[0]), "+f"(c[1]), "+f"(c[2]), "+f"(c[3])
        : "r"(a[0]), "r"(a[1]), "r"(a[2]), "r"(a[3]), "r"(b[0]), "r"(b[1]));
}

// ---- workspace (static device arrays; no allocation) ----
__device__ float g_q[(size_t)TT * HID];
__device__ float g_k[(size_t)TT * HID];
__device__ float g_v[(size_t)TT * HID];
__device__ float g_o[(size_t)TT * HID];
__device__ float g_freq[64];
__device__ __nv_bfloat16 g_xhi[(size_t)TT * HID];
__device__ __nv_bfloat16 g_xlo[(size_t)TT * HID];
__device__ __half        g_xh [(size_t)TT * HID];
__device__ __nv_bfloat16 g_w1hi[(size_t)HID * HID];
__device__ __nv_bfloat16 g_w1lo[(size_t)HID * HID];
__device__ __nv_bfloat16 g_w2hi[(size_t)HID * HID];
__device__ __nv_bfloat16 g_w2lo[(size_t)HID * HID];
__device__ __half        g_w3h [(size_t)HID * HID];
__device__ __half        g_w4h [(size_t)HID * HID];

__global__ void init_freq_kernel() {
    int i = threadIdx.x;
    if (i < 64) g_freq[i] = (float)exp(-(double)i * (log(10000.0) / 64.0));
}

// ============================================================================
// splits
// ============================================================================
__device__ __forceinline__ void split_bf16(const float* __restrict__ x,
                                           __nv_bfloat16* __restrict__ hi,
                                           __nv_bfloat16* __restrict__ lo, int i)
{
    float4 v = ((const float4*)x)[i];
    float vv[4] = {v.x, v.y, v.z, v.w};
    __nv_bfloat16 h[4], l[4];
#pragma unroll
    for (int j = 0; j < 4; j++) {
        h[j] = __float2bfloat16(vv[j]);
        l[j] = __float2bfloat16(vv[j] - __bfloat162float(h[j]));
    }
    ((__nv_bfloat162*)hi)[2 * i + 0] = __nv_bfloat162(h[0], h[1]);
    ((__nv_bfloat162*)hi)[2 * i + 1] = __nv_bfloat162(h[2], h[3]);
    ((__nv_bfloat162*)lo)[2 * i + 0] = __nv_bfloat162(l[0], l[1]);
    ((__nv_bfloat162*)lo)[2 * i + 1] = __nv_bfloat162(l[2], l[3]);
}
__device__ __forceinline__ void conv_fp16(const float* __restrict__ x,
                                          __half* __restrict__ out, int i)
{
    float4 v = ((const float4*)x)[i];
    ((__half2*)out)[2 * i + 0] = __half2(__float2half(v.x), __float2half(v.y));
    ((__half2*)out)[2 * i + 1] = __half2(__float2half(v.z), __float2half(v.w));
}

// x -> bf16 hi/lo (for Q,K GEMMs) + fp16 single (for V GEMM), one pass
__global__ __launch_bounds__(256) void xsplit3_kernel(const float* __restrict__ x, int n4)
{
    int i = blockIdx.x * blockDim.x + threadIdx.x;
    if (i >= n4) return;
    float4 v = ((const float4*)x)[i];
    float vv[4] = {v.x, v.y, v.z, v.w};
    __nv_bfloat16 h[4], l[4];
    __half f[4];
#pragma unroll
    for (int j = 0; j < 4; j++) {
        h[j] = __float2bfloat16(vv[j]);
        l[j] = __float2bfloat16(vv[j] - __bfloat162float(h[j]));
        f[j] = __float2half(vv[j]);
    }
    ((__nv_bfloat162*)g_xhi)[2 * i + 0] = __nv_bfloat162(h[0], h[1]);
    ((__nv_bfloat162*)g_xhi)[2 * i + 1] = __nv_bfloat162(h[2], h[3]);
    ((__nv_bfloat162*)g_xlo)[2 * i + 0] = __nv_bfloat162(l[0], l[1]);
    ((__nv_bfloat162*)g_xlo)[2 * i + 1] = __nv_bfloat162(l[2], l[3]);
    ((__half2*)g_xh)[2 * i + 0] = __half2(f[0], f[1]);
    ((__half2*)g_xh)[2 * i + 1] = __half2(f[2], f[3]);
}

// attention output -> fp16 single (for O GEMM)
__global__ __launch_bounds__(256) void osplit_kernel(int n4)
{
    int i = blockIdx.x * blockDim.x + threadIdx.x;
    if (i >= n4) return;
    conv_fp16(g_o, g_xh, i);
}

// all 4 weight matrices in one launch (blockIdx.z selects); Wq/Wk bf16 pair, Wv/Wo fp16
__global__ __launch_bounds__(256) void wsplit_kernel(
    const float* __restrict__ Wq, const float* __restrict__ Wk,
    const float* __restrict__ Wv, const float* __restrict__ Wo)
{
    int i = blockIdx.x * blockDim.x + threadIdx.x;
    const int n4 = HID * HID / 4;
    if (i >= n4) return;
    int z = blockIdx.z;
    if (z == 0)      split_bf16(Wq, g_w1hi, g_w1lo, i);
    else if (z == 1) split_bf16(Wk, g_w2hi, g_w2lo, i);
    else if (z == 2) conv_fp16(Wv, g_w3h, i);
    else             conv_fp16(Wo, g_w4h, i);
}

// ============================================================================
// GEMM common geometry: CTA 128x128, BK=64, 8 warps (2x4), warp tile 64x32,
// cp.async 3-stage, single __syncthreads per iteration (R7 pipeline).
// ============================================================================
#define TILE_B  16384

// ---- bf16 3-term kernel (Q,K): stage = 4 tiles (Ahi,Alo,Bhi,Blo) ----
#define STAGE3_B (4 * TILE_B)
#define GEMM3_SMEM (3 * STAGE3_B)   // 196608

__global__ __launch_bounds__(256)
void gemm3(const __nv_bfloat16* __restrict__ Ahi, const __nv_bfloat16* __restrict__ Alo,
           const __nv_bfloat16* __restrict__ Bhi, const __nv_bfloat16* __restrict__ Blo,
           const float* __restrict__ bias, float* __restrict__ C)
{
    extern __shared__ char smem[];
    const uint32_t sb = smem_to_u32(smem);
    const int tid = threadIdx.x;
    const int wid = tid >> 5;
    const int lane = tid & 31;
    const int m0 = blockIdx.y << 7;
    const int n0 = blockIdx.x << 7;
    const int wm = wid >> 2;
    const int wn = wid & 3;

    const int lrow = tid >> 1;
    const int lcb  = (tid & 1) * 4;
    const uint32_t lrsw = (uint32_t)(lrow & 7) << 4;
    const __nv_bfloat16* gsrc[4];
    gsrc[0] = Ahi + (size_t)(m0 + lrow) * HID + lcb * 8;
    gsrc[1] = Alo + (size_t)(m0 + lrow) * HID + lcb * 8;
    gsrc[2] = Bhi + (size_t)(n0 + lrow) * HID + lcb * 8;
    gsrc[3] = Blo + (size_t)(n0 + lrow) * HID + lcb * 8;
    uint32_t ldst[4][4];
#pragma unroll
    for (int t = 0; t < 4; t++)
#pragma unroll
        for (int j = 0; j < 4; j++)
            ldst[t][j] = t * TILE_B + lrow * 128 + ((uint32_t)((lcb + j) * 16) ^ lrsw);

    uint32_t a_off[4], a_sw[4];
#pragma unroll
    for (int mt = 0; mt < 4; mt++) {
        int m = wm * 64 + mt * 16 + (lane & 15);
        a_off[mt] = (uint32_t)m * 128;
        a_sw[mt]  = (uint32_t)(m & 7) << 4;
    }
    const uint32_t ka = (uint32_t)((lane >> 4) << 4);
    uint32_t b_off[2], b_sw[2];
#pragma unroll
    for (int p = 0; p < 2; p++) {
        int n = wn * 32 + p * 16 + (lane & 7) + ((lane & 16) >> 1);
        b_off[p] = (uint32_t)n * 128;
        b_sw[p]  = (uint32_t)(n & 7) << 4;
    }
    const uint32_t kb = (uint32_t)((lane & 8) << 1);

    float acc[4][4][4];
#pragma unroll
    for (int i = 0; i < 4; i++)
#pragma unroll
        for (int j = 0; j < 4; j++)
#pragma unroll
            for (int k = 0; k < 4; k++) acc[i][j][k] = 0.f;

#pragma unroll
    for (int s = 0; s < 2; s++) {
        uint32_t base = sb + s * STAGE3_B;
#pragma unroll
        for (int t = 0; t < 4; t++) {
            const __nv_bfloat16* src = gsrc[t] + s * 64;
#pragma unroll
            for (int j = 0; j < 4; j++)
                cp16(base + ldst[t][j], src + j * 8);
        }
        CP_COMMIT();
    }

    for (int c = 0; c < 64; c++) {
        CP_WAIT1();
        __syncthreads();
        const int ldc = c + 2;
        if (ldc < 64) {
            uint32_t base = sb + (ldc % 3) * STAGE3_B;
#pragma unroll
            for (int t = 0; t < 4; t++) {
                const __nv_bfloat16* src = gsrc[t] + ldc * 64;
#pragma unroll
                for (int j = 0; j < 4; j++)
                    cp16(base + ldst[t][j], src + j * 8);
            }
        }
        CP_COMMIT();

        const uint32_t stb = sb + (c % 3) * STAGE3_B;
#pragma unroll
        for (int ks = 0; ks < 4; ks++) {
            uint32_t ahi[4][4], alo[4][4];
#pragma unroll
            for (int mt = 0; mt < 4; mt++) {
                uint32_t ko = ((uint32_t)(ks * 32) + ka) ^ a_sw[mt];
                uint32_t ad = stb + a_off[mt] + ko;
                ldsm4(ahi[mt], ad);
                ldsm4(alo[mt], ad + TILE_B);
            }
            uint32_t bhi[2][4], blo[2][4];
#pragma unroll
            for (int p = 0; p < 2; p++) {
                uint32_t ko = ((uint32_t)(ks * 32) + kb) ^ b_sw[p];
                uint32_t bd = stb + 2 * TILE_B + b_off[p] + ko;
                ldsm4(bhi[p], bd);
                ldsm4(blo[p], bd + TILE_B);
            }
#pragma unroll
            for (int mt = 0; mt < 4; mt++)
#pragma unroll
                for (int nt = 0; nt < 4; nt++) {
                    const uint32_t* bh = &bhi[nt >> 1][2 * (nt & 1)];
                    const uint32_t* bl = &blo[nt >> 1][2 * (nt & 1)];
                    mma_bf16(acc[mt][nt], ahi[mt], bh);
                    mma_bf16(acc[mt][nt], ahi[mt], bl);
                    mma_bf16(acc[mt][nt], alo[mt], bh);
                }
        }
    }

#pragma unroll
    for (int mt = 0; mt < 4; mt++) {
#pragma unroll
        for (int nt = 0; nt < 4; nt++) {
            int row = m0 + wm * 64 + mt * 16 + (lane >> 2);
            int col = n0 + wn * 32 + nt * 8 + 2 * (lane & 3);
            float2 bv = *(const float2*)&bias[col];
            float2 v0, v1;
            v0.x = acc[mt][nt][0] + bv.x; v0.y = acc[mt][nt][1] + bv.y;
            v1.x = acc[mt][nt][2] + bv.x; v1.y = acc[mt][nt][3] + bv.y;
            *(float2*)&C[(size_t)row * HID + col]       = v0;
            *(float2*)&C[(size_t)(row + 8) * HID + col] = v1;
        }
    }
}

// ---- fp16 1-term kernel (V,O): plain A x B^T; stage = 2 tiles = 32KB ----
// 3 stages = 96KB; regs ~110 -> 2 CTAs/SM (forced via launch_bounds minBlocks=2)
#define STAGE1_B (2 * TILE_B)
#define GEMM1_SMEM (3 * STAGE1_B)   // 98304

__global__ __launch_bounds__(256, 2)
void gemm1h(const __half* __restrict__ A, const __half* __restrict__ B,
            const float* __restrict__ bias, float* __restrict__ C)
{
    extern __shared__ char smem[];
    const uint32_t sb = smem_to_u32(smem);
    const int tid = threadIdx.x;
    const int wid = tid >> 5;
    const int lane = tid & 31;
    const int m0 = blockIdx.y << 7;
    const int n0 = blockIdx.x << 7;
    const int wm = wid >> 2;
    const int wn = wid & 3;

    const int lrow = tid >> 1;
    const int lcb  = (tid & 1) * 4;
    const uint32_t lrsw = (uint32_t)(lrow & 7) << 4;
    const __half* gsrc[2];
    gsrc[0] = A + (size_t)(m0 + lrow) * HID + lcb * 8;
    gsrc[1] = B + (size_t)(n0 + lrow) * HID + lcb * 8;
    uint32_t ldst[2][4];
#pragma unroll
    for (int t = 0; t < 2; t++)
#pragma unroll
        for (int j = 0; j < 4; j++)
            ldst[t][j] = t * TILE_B + lrow * 128 + ((uint32_t)((lcb + j) * 16) ^ lrsw);

    uint32_t a_off[4], a_sw[4];
#pragma unroll
    for (int mt = 0; mt < 4; mt++) {
        int m = wm * 64 + mt * 16 + (lane & 15);
        a_off[mt] = (uint32_t)m * 128;
        a_sw[mt]  = (uint32_t)(m & 7) << 4;
    }
    const uint32_t ka = (uint32_t)((lane >> 4) << 4);
    uint32_t b_off[2], b_sw[2];
#pragma unroll
    for (int p = 0; p < 2; p++) {
        int n = wn * 32 + p * 16 + (lane & 7) + ((lane & 16) >> 1);
        b_off[p] = (uint32_t)n * 128;
        b_sw[p]  = (uint32_t)(n & 7) << 4;
    }
    const uint32_t kb = (uint32_t)((lane & 8) << 1);

    float acc[4][4][4];
#pragma unroll
    for (int i = 0; i < 4; i++)
#pragma unroll
        for (int j = 0; j < 4; j++)
#pragma unroll
            for (int k = 0; k < 4; k++) acc[i][j][k] = 0.f;

#pragma unroll
    for (int s = 0; s < 2; s++) {
        uint32_t base = sb + s * STAGE1_B;
#pragma unroll
        for (int t = 0; t < 2; t++) {
            const __half* src = gsrc[t] + s * 64;
#pragma unroll
            for (int j = 0; j < 4; j++)
                cp16(base + ldst[t][j], src + j * 8);
        }
        CP_COMMIT();
    }

    for (int c = 0; c < 64; c++) {
        CP_WAIT1();
        __syncthreads();
        const int ldc = c + 2;
        if (ldc < 64) {
            uint32_t base = sb + (ldc % 3) * STAGE1_B;
#pragma unroll
            for (int t = 0; t < 2; t++) {
                const __half* src = gsrc[t] + ldc * 64;
#pragma unroll
                for (int j = 0; j < 4; j++)
                    cp16(base + ldst[t][j], src + j * 8);
            }
        }
        CP_COMMIT();

        const uint32_t stb = sb + (c % 3) * STAGE1_B;
#pragma unroll
        for (int ks = 0; ks < 4; ks++) {
            uint32_t af[4][4];
#pragma unroll
            for (int mt = 0; mt < 4; mt++) {
                uint32_t ko = ((uint32_t)(ks * 32) + ka) ^ a_sw[mt];
                ldsm4(af[mt], stb + a_off[mt] + ko);
            }
            uint32_t bf[2][4];
#pragma unroll
            for (int p = 0; p < 2; p++) {
                uint32_t ko = ((uint32_t)(ks * 32) + kb) ^ b_sw[p];
                ldsm4(bf[p], stb + TILE_B + b_off[p] + ko);
            }
#pragma unroll
            for (int mt = 0; mt < 4; mt++)
#pragma unroll
                for (int nt = 0; nt < 4; nt++)
                    mma_fp16(acc[mt][nt], af[mt], &bf[nt >> 1][2 * (nt & 1)]);
        }
    }

#pragma unroll
    for (int mt = 0; mt < 4; mt++) {
#pragma unroll
        for (int nt = 0; nt < 4; nt++) {
            int row = m0 + wm * 64 + mt * 16 + (lane >> 2);
            int col = n0 + wn * 32 + nt * 8 + 2 * (lane & 3);
            float2 bv = *(const float2*)&bias[col];
            float2 v0, v1;
            v0.x = acc[mt][nt][0] + bv.x; v0.y = acc[mt][nt][1] + bv.y;
            v1.x = acc[mt][nt][2] + bv.x; v1.y = acc[mt][nt][3] + bv.y;
            *(float2*)&C[(size_t)row * HID + col]       = v0;
            *(float2*)&C[(size_t)(row + 8) * HID + col] = v1;
        }
    }
}

// ============================================================================
// RoPE on packed q,k in place (angle in f32 like reference, trig in double)
// ============================================================================
__global__ void rope_kernel(const int* __restrict__ pos) {
    int idx = blockIdx.x * blockDim.x + threadIdx.x;
    if (idx >= TT * NH * 64) return;
    int i = idx & 63;
    int h = (idx >> 6) & 31;
    int t = idx >> 11;
    float p = (float)pos[t];
    float ang = p * g_freq[i];
    double ad = (double)ang;
    float c = (float)cos(ad);
    float s = (float)sin(ad);
    size_t base = ((size_t)t * NH + h) * HD;
    float x1 = g_q[base + i], x2 = g_q[base + 64 + i];
    g_q[base + i]      = x1 * c - x2 * s;
    g_q[base + 64 + i] = x2 * c + x1 * s;
    float y1 = g_k[base + i], y2 = g_k[base + 64 + i];
    g_k[base + i]      = y1 * c - y2 * s;
    g_k[base + 64 + i] = y2 * c + y1 * s;
}

// ============================================================================
// Flash attention (fp32), validated in round 1
// ============================================================================
#define ATTN_SMEM_FLOATS (8192 + 8448 + 4224 + 192)
#define ATTN_SMEM_BYTES  (ATTN_SMEM_FLOATS * 4)

__global__ __launch_bounds__(128) void attn_kernel(
    const float* __restrict__ past_k, const float* __restrict__ past_v,
    const int* __restrict__ q_start, const int* __restrict__ q_lens,
    const int* __restrict__ kv_lens, const int* __restrict__ boff)
{
    extern __shared__ float sm[];
    float* Qs   = sm;
    float* KVs  = sm + 8192;
    float* Ps   = KVs + 8448;
    float* mrow = Ps + 4224;
    float* lrow = mrow + 64;
    float* arow = lrow + 64;

    const int b = blockIdx.z, h = blockIdx.y, qt = blockIdx.x;
    const int qlen = q_lens[b];
    if (qt * 64 >= qlen) return;
    const int qs0 = q_start[b];
    const int kvlen = kv_lens[b];
    const int hist = kvlen - qlen;
    const int tid = threadIdx.x;
    const float scale = 0.08838834764831845f;
    const float NEGINF = __int_as_float(0xff800000);

    const int c4 = (tid & 31) << 2;
    const int r0 = tid >> 5;

#pragma unroll
    for (int rr = 0; rr < 16; rr++) {
        int r = r0 + rr * 4;
        int qglob = qt * 64 + r;
        float4 v = make_float4(0.f, 0.f, 0.f, 0.f);
        if (qglob < qlen)
            v = *(const float4*)&g_q[((size_t)(qs0 + qglob) * NH + h) * HD + c4];
        *(float4*)&Qs[r * 128 + c4] = v;
    }
    if (tid < 64) { mrow[tid] = NEGINF; lrow[tid] = 0.f; }
    __syncthreads();

    const int tq = tid >> 3;
    const int tk = tid & 7;

    float o[4][16];
#pragma unroll
    for (int i = 0; i < 4; i++)
#pragma unroll
        for (int j = 0; j < 16; j++) o[i][j] = 0.f;

    const int qhi  = min(qt * 64 + 63, qlen - 1);
    const int nblk = min((kvlen + 63) >> 6, ((hist + qhi) >> 6) + 1);

    for (int kb = 0; kb < nblk; kb++) {
#pragma unroll
        for (int rr = 0; rr < 16; rr++) {
            int r = r0 + rr * 4;
            int p = kb * 64 + r;
            int pc = min(p, kvlen - 1);
            const float* src;
            if (pc < hist) {
                int blk = boff[b * MAXB + (pc >> 6)];
                src = past_k + ((size_t)(blk * 64 + (pc & 63)) * NH + h) * HD;
            } else {
                src = g_k + ((size_t)(qs0 + pc - hist) * NH + h) * HD;
            }
            *(float4*)&KVs[r * 132 + c4] = *(const float4*)&src[c4];
        }
        __syncthreads();

        float s[4][8];
#pragma unroll
        for (int i = 0; i < 4; i++)
#pragma unroll
            for (int m = 0; m < 8; m++) s[i][m] = 0.f;
#pragma unroll 4
        for (int d = 0; d < 128; d += 4) {
            float4 qv[4];
#pragma unroll
            for (int i = 0; i < 4; i++)
                qv[i] = *(const float4*)&Qs[(tq * 4 + i) * 128 + d];
#pragma unroll
            for (int m = 0; m < 8; m++) {
                float4 kv = *(const float4*)&KVs[(tk + 8 * m) * 132 + d];
#pragma unroll
                for (int i = 0; i < 4; i++)
                    s[i][m] += qv[i].x * kv.x + qv[i].y * kv.y + qv[i].z * kv.z + qv[i].w * kv.w;
            }
        }
#pragma unroll
        for (int i = 0; i < 4; i++) {
            int qglob = qt * 64 + tq * 4 + i;
#pragma unroll
            for (int m = 0; m < 8; m++) {
                int kg = kb * 64 + tk + 8 * m;
                float val = (kg <= hist + qglob) ? s[i][m] * scale : NEGINF;
                Ps[(tq * 4 + i) * 66 + tk + 8 * m] = val;
            }
        }
        __syncthreads();

#pragma unroll
        for (int rr = 0; rr < 16; rr++) {
            int r = r0 + rr * 4;
            int p = kb * 64 + r;
            int pc = min(p, kvlen - 1);
            const float* src;
            if (pc < hist) {
                int blk = boff[b * MAXB + (pc >> 6)];
                src = past_v + ((size_t)(blk * 64 + (pc & 63)) * NH + h) * HD;
            } else {
                src = g_v + ((size_t)(qs0 + pc - hist) * NH + h) * HD;
            }
            *(float4*)&KVs[r * 132 + c4] = *(const float4*)&src[c4];
        }

        if (tid < 64) {
            int r = tid;
            float mo = mrow[r];
            float mx = mo;
#pragma unroll 8
            for (int j = 0; j < 64; j++) mx = fmaxf(mx, Ps[r * 66 + j]);
            float alpha = expf(mo - mx);
            float sum = 0.f;
#pragma unroll 8
            for (int j = 0; j < 64; j++) {
                float pj = expf(Ps[r * 66 + j] - mx);
                Ps[r * 66 + j] = pj;
                sum += pj;
            }
            mrow[r] = mx;
            lrow[r] = lrow[r] * alpha + sum;
            arow[r] = alpha;
        }
        __syncthreads();

#pragma unroll
        for (int i = 0; i < 4; i++) {
            float a = arow[tq * 4 + i];
#pragma unroll
            for (int j = 0; j < 16; j++) o[i][j] *= a;
        }
#pragma unroll 2
        for (int k = 0; k < 64; k++) {
            float pr[4];
#pragma unroll
            for (int i = 0; i < 4; i++) pr[i] = Ps[(tq * 4 + i) * 66 + k];
#pragma unroll
            for (int m = 0; m < 4; m++) {
                float4 vv = *(const float4*)&KVs[k * 132 + tk * 4 + 32 * m];
#pragma unroll
                for (int i = 0; i < 4; i++) {
                    o[i][m * 4 + 0] += pr[i] * vv.x;
                    o[i][m * 4 + 1] += pr[i] * vv.y;
                    o[i][m * 4 + 2] += pr[i] * vv.z;
                    o[i][m * 4 + 3] += pr[i] * vv.w;
                }
            }
        }
        __syncthreads();
    }

#pragma unroll
    for (int i = 0; i < 4; i++) {
        int qglob = qt * 64 + tq * 4 + i;
        if (qglob >= qlen) continue;
        float inv = 1.f / lrow[tq * 4 + i];
        size_t base = ((size_t)(qs0 + qglob) * NH + h) * HD;
#pragma unroll
        for (int m = 0; m < 4; m++) {
            float4 w;
            w.x = o[i][m * 4 + 0] * inv;
            w.y = o[i][m * 4 + 1] * inv;
            w.z = o[i][m * 4 + 2] * inv;
            w.w = o[i][m * 4 + 3] * inv;
            *(float4*)&g_o[base + tk * 4 + 32 * m] = w;
        }
    }
}

// ============================================================================
extern "C" void kernel_launch(void* const* d_in, const int* in_sizes, int n_in,
                              void* d_out, int out_size) {
    const float* x      = (const float*)d_in[0];
    const int*   pos    = (const int*)d_in[1];
    const int*   qstart = (const int*)d_in[2];
    const int*   qlens  = (const int*)d_in[3];
    const int*   kvlens = (const int*)d_in[4];
    const int*   boff   = (const int*)d_in[5];
    const float* pk     = (const float*)d_in[6];
    const float* pv     = (const float*)d_in[7];
    const float* Wq = (const float*)d_in[8];
    const float* bq = (const float*)d_in[9];
    const float* Wk = (const float*)d_in[10];
    const float* bk = (const float*)d_in[11];
    const float* Wv = (const float*)d_in[12];
    const float* bv = (const float*)d_in[13];
    const float* Wo = (const float*)d_in[14];
    const float* bo = (const float*)d_in[15];
    float* out = (float*)d_out;

    float *qp, *kp, *vp;
    cudaGetSymbolAddress((void**)&qp, g_q);
    cudaGetSymbolAddress((void**)&kp, g_k);
    cudaGetSymbolAddress((void**)&vp, g_v);
    __nv_bfloat16 *xhi, *xlo, *w1hi, *w1lo, *w2hi, *w2lo;
    __half *xh, *w3h, *w4h;
    cudaGetSymbolAddress((void**)&xhi, g_xhi);
    cudaGetSymbolAddress((void**)&xlo, g_xlo);
    cudaGetSymbolAddress((void**)&xh,  g_xh);
    cudaGetSymbolAddress((void**)&w1hi, g_w1hi);
    cudaGetSymbolAddress((void**)&w1lo, g_w1lo);
    cudaGetSymbolAddress((void**)&w2hi, g_w2hi);
    cudaGetSymbolAddress((void**)&w2lo, g_w2lo);
    cudaGetSymbolAddress((void**)&w3h, g_w3h);
    cudaGetSymbolAddress((void**)&w4h, g_w4h);

    cudaFuncSetAttribute(gemm3,  cudaFuncAttributeMaxDynamicSharedMemorySize, GEMM3_SMEM);
    cudaFuncSetAttribute(gemm1h, cudaFuncAttributeMaxDynamicSharedMemorySize, GEMM1_SMEM);
    cudaFuncSetAttribute(attn_kernel, cudaFuncAttributeMaxDynamicSharedMemorySize, ATTN_SMEM_BYTES);

    const int n4x = TT * HID / 4;
    const int n4w = HID * HID / 4;
    dim3 gg(HID / 128, TT / 128);   // (32, 24)

    // 0: weight splits, 1: activation split (bf16 pair + fp16)
    wsplit_kernel<<<dim3((n4w + 255) / 256, 1, 4), 256>>>(Wq, Wk, Wv, Wo);
    xsplit3_kernel<<<(n4x + 255) / 256, 256>>>(x, n4x);
    // 2,3: Q/K GEMMs (bf16 3-term), 4: V GEMM (fp16 1-term)
    gemm3<<<gg, 256, GEMM3_SMEM>>>(xhi, xlo, w1hi, w1lo, bq, qp);
    gemm3<<<gg, 256, GEMM3_SMEM>>>(xhi, xlo, w2hi, w2lo, bk, kp);
    gemm1h<<<gg, 256, GEMM1_SMEM>>>(xh, w3h, bv, vp);
    // 5: freq, 6: rope, 7: attention
    init_freq_kernel<<<1, 64>>>();
    rope_kernel<<<(TT * NH * 64 + 255) / 256, 256>>>(pos);
    attn_kernel<<<dim3(16, NH, NBAT), 128, ATTN_SMEM_BYTES>>>(pk, pv, qstart, qlens,
                                                              kvlens, boff);
    // 8: attention output -> fp16, 9: O GEMM (fp16 1-term)
    osplit_kernel<<<(n4x + 255) / 256, 256>>>(n4x);
    gemm1h<<<gg, 256, GEMM1_SMEM>>>(xh, w4h, bo, out);
}